// round 13
// baseline (speedup 1.0000x reference)
#include <cuda_runtime.h>
#include <cuda_bf16.h>
#include <cstdint>

// Problem dims
#define BB   128
#define TT   512
#define HH   256
#define H2   512
#define LIN  200
#define LPAD 208          // 13 k-tiles * 16
#define FEAT 582
#define FPAD 592          // 37 k-tiles * 16
#define G4   1024
#define SP   58
#define KV   768          // 256 + 512

#define CLS  8            // cluster size (CTAs per cluster)

typedef unsigned long long u64;

// ---------------- device scratch ----------------
__device__ float g_csum [BB * TT * H2];
__device__ float g_feats[BB * TT * FPAD];
__device__ float g_z    [BB * TT * LPAD];
__device__ float g_G0   [BB * TT * G4];
__device__ float g_hs   [BB * TT * HH];
__device__ float g_fcW  [LIN * FPAD];     // zero-padded fc_W
__device__ float g_Wih  [G4 * LPAD];      // zero-padded W_ih
__device__ int   g_lastsep[BB * TT];

__device__ __forceinline__ float sigf(float x) { return 1.f / (1.f + __expf(-x)); }
__device__ __forceinline__ float tanhfast(float x) {
    float e = __expf(2.f * x);
    return 1.f - 2.f / (e + 1.f);
}

// packed fp32x2 helpers (sm_100+: fma.rn.f32x2)
__device__ __forceinline__ u64 ffma2(u64 a, u64 b, u64 c) {
    u64 d; asm("fma.rn.f32x2 %0, %1, %2, %3;" : "=l"(d) : "l"(a), "l"(b), "l"(c)); return d;
}
__device__ __forceinline__ u64 pack2(float lo, float hi) {
    u64 d; asm("mov.b64 %0, {%1, %2};" : "=l"(d) : "f"(lo), "f"(hi)); return d;
}
__device__ __forceinline__ float2 unpack2(u64 v) {
    float lo, hi; asm("mov.b64 {%0, %1}, %2;" : "=f"(lo), "=f"(hi) : "l"(v));
    return make_float2(lo, hi);
}
__device__ __forceinline__ uint32_t smem_u32(const void* p) {
    uint32_t a;
    asm("{ .reg .u64 t; cvta.to.shared.u64 t, %1; cvt.u32.u64 %0, t; }" : "=r"(a) : "l"(p));
    return a;
}

// ---------------- kernel 1: csum (512 blk) + lastsep + weight padding (8 blk)
__global__ void __launch_bounds__(128) prep_k(const float* __restrict__ enc,
                                              const int* __restrict__ sep,
                                              const float* __restrict__ fcW,
                                              const float* __restrict__ Wih) {
    const int blk = blockIdx.x;
    if (blk >= 512) {
        const int tid = (blk - 512) * 128 + threadIdx.x;   // 0..1023
        for (int i = tid; i < LIN * FPAD; i += 1024) {
            const int n = i / FPAD, k = i - n * FPAD;
            g_fcW[i] = (k < FEAT) ? fcW[n * FEAT + k] : 0.f;
        }
        for (int i = tid; i < G4 * LPAD; i += 1024) {
            const int n = i / LPAD, k = i - n * LPAD;
            g_Wih[i] = (k < LIN) ? Wih[n * LIN + k] : 0.f;
        }
        return;
    }
    const int b = blk >> 2;
    const int ch = (blk & 3) * 128 + threadIdx.x;
    const float* e = enc + (long long)b * TT * H2 + ch;
    float* cs = g_csum + (long long)b * TT * H2 + ch;
    float run = 0.f;
    #pragma unroll 8
    for (int t = 0; t < TT; t++) {
        cs[t * H2] = run;
        run += e[t * H2];
    }
    if ((blk & 3) == 0 && threadIdx.x == 0) {
        int cm = 0;
        const int* sp = sep + b * TT;
        int* ls = g_lastsep + b * TT;
        #pragma unroll 4
        for (int t = 0; t < TT; t++) {
            ls[t] = cm;
            if (sp[t] > 0) cm = t;
        }
    }
}

// ---------------- kernel 2: build features (padded to FPAD with zeros) -------
__global__ void __launch_bounds__(128) feats_k(const int* __restrict__ pos_ids,
                                               const float* __restrict__ pos_emb,
                                               const float* __restrict__ wordlen_emb) {
    const int m = blockIdx.x;             // b*T + t
    const int b = m >> 9;
    const int t = m & (TT - 1);
    const int ls = g_lastsep[m];
    int wlen = t - ls; if (wlen < 1) wlen = 1;
    const int wid = (wlen < 7) ? wlen : 7;
    const int lp = pos_ids[b * TT + ls];
    const float inv = 1.0f / (float)wlen;
    float* f = g_feats + (long long)m * FPAD;
    const float* ct = g_csum + ((long long)b * TT + t) * H2;
    const float* cs = g_csum + ((long long)b * TT + ls) * H2;
    for (int i = threadIdx.x; i < FPAD; i += 128) {
        float v;
        if (i < 50)       v = pos_emb[lp * 50 + i];
        else if (i < 562) { int k = i - 50; v = (ct[k] - cs[k]) * inv; }
        else if (i < 582) v = wordlen_emb[wid * 20 + (i - 562)];
        else              v = 0.f;
        f[i] = v;
    }
}

// ---------------- fp32 GEMM with FFMA2: C[M,N] = A[M,K] * B[N,K]^T ----------
// BM=128, BN=64, BK=16, 128 threads, 8x8 microtile (pairs along m).
template<int MODE, bool KMUL16>
__global__ void __launch_bounds__(128) gemm_k(
    const float* __restrict__ A, const float* __restrict__ Bm,
    const float* __restrict__ bias1, const float* __restrict__ bias2,
    const float* __restrict__ enc, const int* __restrict__ length,
    float* __restrict__ C, int N, int K, int lda, int ldb, int ldc, int nstore)
{
    __shared__ __align__(16) float Asm[16][132];
    __shared__ __align__(16) float Bsm[16][72];
    const int n0 = blockIdx.x * 64;
    const int m0 = blockIdx.y * 128;
    const int tid = threadIdx.x;
    const int tx = tid & 7, ty = tid >> 3;

    const int arow = tid >> 2;          // 0..31
    const int akq  = (tid & 3) * 4;     // 0,4,8,12
    const int brow = tid >> 1;          // 0..63
    const int bk0  = (tid & 1) * 8;     // 0 or 8

    u64 acc[4][8];
    #pragma unroll
    for (int p = 0; p < 4; p++)
        #pragma unroll
        for (int q = 0; q < 8; q++) acc[p][q] = 0ull;

    float bsum[8];
    #pragma unroll
    for (int q = 0; q < 8; q++) {
        const int n = n0 + tx * 8 + q;
        if (MODE == 1)      bsum[q] = (n < N) ? bias1[n] : 0.f;
        else if (MODE == 2) bsum[q] = bias1[n] + bias2[n];
        else                bsum[q] = 0.f;
    }

    const int nkt = (K + 15) >> 4;

    float4 ra[4], rb[2], na[4], nb[2];

    auto loadA = [&](int kt, float4* r) {
        const int k = kt * 16 + akq;
        #pragma unroll
        for (int p = 0; p < 4; p++) {
            const int m = m0 + arow + p * 32;
            if (MODE == 3) {
                const float* src = (k < 256) ? (A + (long long)m * 256 + k)
                                             : (enc + (long long)m * 512 + (k - 256));
                r[p] = *reinterpret_cast<const float4*>(src);
            } else {
                r[p] = *reinterpret_cast<const float4*>(A + (long long)m * lda + k);
            }
        }
    };
    auto loadB = [&](int kt, float4* r) {
        const int n = n0 + brow;
        #pragma unroll
        for (int q = 0; q < 2; q++) {
            const int k = kt * 16 + bk0 + q * 4;
            float4 v = make_float4(0.f, 0.f, 0.f, 0.f);
            if (n < N) {
                if (KMUL16 || k + 3 < K) {
                    v = *reinterpret_cast<const float4*>(Bm + (long long)n * ldb + k);
                } else {
                    float t4[4];
                    #pragma unroll
                    for (int i = 0; i < 4; i++)
                        t4[i] = (k + i < K) ? Bm[(long long)n * ldb + k + i] : 0.f;
                    v = make_float4(t4[0], t4[1], t4[2], t4[3]);
                }
            }
            r[q] = v;
        }
    };

    loadA(0, ra); loadB(0, rb);
    for (int kt = 0; kt < nkt; kt++) {
        #pragma unroll
        for (int p = 0; p < 4; p++) {
            Asm[akq + 0][arow + p * 32] = ra[p].x;
            Asm[akq + 1][arow + p * 32] = ra[p].y;
            Asm[akq + 2][arow + p * 32] = ra[p].z;
            Asm[akq + 3][arow + p * 32] = ra[p].w;
        }
        #pragma unroll
        for (int q = 0; q < 2; q++) {
            Bsm[bk0 + q * 4 + 0][brow] = rb[q].x;
            Bsm[bk0 + q * 4 + 1][brow] = rb[q].y;
            Bsm[bk0 + q * 4 + 2][brow] = rb[q].z;
            Bsm[bk0 + q * 4 + 3][brow] = rb[q].w;
        }
        __syncthreads();
        if (kt + 1 < nkt) { loadA(kt + 1, na); loadB(kt + 1, nb); }
        #pragma unroll
        for (int kk = 0; kk < 16; kk++) {
            const ulonglong2 a01 = *reinterpret_cast<const ulonglong2*>(&Asm[kk][ty * 8]);
            const ulonglong2 a23 = *reinterpret_cast<const ulonglong2*>(&Asm[kk][ty * 8 + 4]);
            const float4 b0 = *reinterpret_cast<const float4*>(&Bsm[kk][tx * 8]);
            const float4 b1 = *reinterpret_cast<const float4*>(&Bsm[kk][tx * 8 + 4]);
            u64 av[4] = {a01.x, a01.y, a23.x, a23.y};
            u64 bd[8] = {pack2(b0.x, b0.x), pack2(b0.y, b0.y), pack2(b0.z, b0.z), pack2(b0.w, b0.w),
                         pack2(b1.x, b1.x), pack2(b1.y, b1.y), pack2(b1.z, b1.z), pack2(b1.w, b1.w)};
            #pragma unroll
            for (int p = 0; p < 4; p++)
                #pragma unroll
                for (int q = 0; q < 8; q++)
                    acc[p][q] = ffma2(av[p], bd[q], acc[p][q]);
        }
        __syncthreads();
        #pragma unroll
        for (int p = 0; p < 4; p++) ra[p] = na[p];
        rb[0] = nb[0]; rb[1] = nb[1];
    }

    const bool vec = (MODE == 2) || (MODE == 1 && n0 + 64 <= N);
    #pragma unroll
    for (int p = 0; p < 4; p++) {
        float2 fr[8];
        #pragma unroll
        for (int q = 0; q < 8; q++) fr[q] = unpack2(acc[p][q]);
        #pragma unroll
        for (int half = 0; half < 2; half++) {
            const int m = m0 + ty * 8 + p * 2 + half;
            const int t = m & (TT - 1);
            float vals[8];
            int lenb = 0;
            if (MODE == 3) lenb = length[m >> 9];
            #pragma unroll
            for (int q = 0; q < 8; q++) {
                const int n = n0 + tx * 8 + q;
                float v = half ? fr[q].y : fr[q].x;
                if (MODE == 1) {
                    if (n < N) { v = tanhfast(v + bsum[q]); if (t == 0) v = 0.f; }
                    else v = 0.f;
                } else if (MODE == 2) {
                    v += bsum[q];
                } else {
                    if (t >= lenb) v = 0.f;
                    if (t == 0 && n == 0) v = -1e30f;
                }
                vals[q] = v;
            }
            float* cp = C + (long long)m * ldc + n0 + tx * 8;
            if (vec) {
                *reinterpret_cast<float4*>(cp)     = make_float4(vals[0], vals[1], vals[2], vals[3]);
                *reinterpret_cast<float4*>(cp + 4) = make_float4(vals[4], vals[5], vals[6], vals[7]);
            } else {
                #pragma unroll
                for (int q = 0; q < 8; q++) {
                    const int n = n0 + tx * 8 + q;
                    if (n < nstore) cp[q] = vals[q];
                }
            }
        }
    }
}

// ---------------- persistent LSTM recurrence: clusters + DSMEM --------------
// 16 clusters x 8 CTAs. Cluster ci owns batches ci*8..ci*8+7.
// CTA rank r owns hidden units j = r*32 .. r*32+31 (128 W_hh rows in smem).
// 512 threads: tid = jj*16 + gp*8 + b  (jj 0..31, gp 0..1 gate-pair, b 0..7).
// h exchange: st.shared::cluster into every CTA's double-buffered Hsm, then
// barrier.cluster (release/acquire). No L2 traffic in the recurrence loop.
#define WROWS   128
#define WSTR    260
#define HBUF    (8 * WSTR)                  // one h buffer: 8 batches x 260
__global__ void __launch_bounds__(512, 1) __cluster_dims__(CLS, 1, 1)
lstm_k(const float* __restrict__ W_hh) {
    extern __shared__ float sm[];
    float* Wsm = sm;                        // [128][260]
    float* Hsm = sm + WROWS * WSTR;         // [2][8][260]
    const int tid = threadIdx.x;
    const int jj = tid >> 4;                // 0..31
    const int gp = (tid >> 3) & 1;          // 0..1
    const int b  = tid & 7;                 // 0..7
    uint32_t rank; asm("mov.u32 %0, %%cluster_ctarank;" : "=r"(rank));
    const int ci = blockIdx.x >> 3;
    const int bglob = ci * 8 + b;
    const int jglob = (int)rank * 32 + jj;

    // load W slice: smem row (lj*4 + g) <- W_hh[g*256 + rank*32 + lj]
    #pragma unroll
    for (int i = 0; i < 16; i++) {
        const int idx = tid + i * 512;      // 0..8191
        const int row = idx >> 6, k4 = idx & 63;
        const int lj = row >> 2, g = row & 3;
        const float4 w = reinterpret_cast<const float4*>(W_hh)
                             [(g * 256 + (int)rank * 32 + lj) * 64 + k4];
        *reinterpret_cast<float4*>(&Wsm[row * WSTR + k4 * 4]) = w;
    }
    // zero both h buffers
    for (int i = tid; i < 2 * HBUF; i += 512) Hsm[i] = 0.f;

    // precompute remote addresses of our h slot (buffer 0) in all 8 CTAs
    const uint32_t hlocal = smem_u32(&Hsm[b * WSTR + jglob]);
    uint32_t ra[CLS];
    #pragma unroll
    for (int r = 0; r < CLS; r++)
        asm("mapa.shared::cluster.u32 %0, %1, %2;" : "=r"(ra[r]) : "r"(hlocal), "r"(r));

    float c = 0.f;
    // prefetch G0 for t=0: gates (2gp, 2gp+1)
    float pg0, pg1;
    {
        const float* G = g_G0 + (long long)(bglob * TT) * G4 + jglob + gp * 512;
        pg0 = G[0]; pg1 = G[256];
    }
    asm volatile("barrier.cluster.arrive.aligned;" ::: "memory");
    asm volatile("barrier.cluster.wait.aligned;" ::: "memory");

    const float* Wr0 = &Wsm[(jj * 4 + 2 * gp) * WSTR];
    const float* Wr1 = Wr0 + WSTR;

    for (int t = 0; t < TT; t++) {
        const float* Hr = &Hsm[(t & 1) * HBUF + b * WSTR];
        u64 acc0 = pack2(pg0, 0.f);
        u64 acc1 = pack2(pg1, 0.f);
        if (t + 1 < TT) {
            const float* G = g_G0 + (long long)(bglob * TT + t + 1) * G4 + jglob + gp * 512;
            pg0 = G[0]; pg1 = G[256];
        }
        #pragma unroll 16
        for (int k4 = 0; k4 < 64; k4++) {
            const ulonglong2 h2 = *reinterpret_cast<const ulonglong2*>(Hr + k4 * 4);
            ulonglong2 w;
            w = *reinterpret_cast<const ulonglong2*>(Wr0 + k4 * 4);
            acc0 = ffma2(h2.x, w.x, acc0); acc0 = ffma2(h2.y, w.y, acc0);
            w = *reinterpret_cast<const ulonglong2*>(Wr1 + k4 * 4);
            acc1 = ffma2(h2.x, w.x, acc1); acc1 = ffma2(h2.y, w.y, acc1);
        }
        const float2 f0 = unpack2(acc0);
        const float2 f1 = unpack2(acc1);
        const float s0 = f0.x + f0.y;          // gp0: i-sum   gp1: g-sum
        const float s1 = f1.x + f1.y;          // gp0: f-sum   gp1: o-sum
        // branchless: sig(x) = 0.5*tanh(x/2)+0.5
        const float scl = gp ? 1.0f : 0.5f;
        const float off = gp ? 0.0f : 0.5f;
        const float a0 = tanhfast(s0 * scl) * scl + off;   // gp0: sig(i)  gp1: tanh(g)
        const float a1 = sigf(s1);                          // gp0: sig(f)  gp1: sig(o)
        const float e0 = __shfl_xor_sync(0xffffffffu, a0, 8);
        const float e1 = __shfl_xor_sync(0xffffffffu, a1, 8);
        const float si = gp ? e0 : a0;
        const float sf = gp ? e1 : a1;
        const float tg = gp ? a0 : e0;
        const float so = gp ? a1 : e1;
        c = sf * c + si * tg;
        const float hv = so * tanhfast(c);

        // distribute h to all cluster CTAs' next buffer; gp1 writes hs to gmem
        const uint32_t off16 = (uint32_t)(((t + 1) & 1) * (HBUF * 4));
        if (gp == 0) {
            #pragma unroll
            for (int r = 0; r < CLS; r++)
                asm volatile("st.shared::cluster.f32 [%0], %1;"
                             :: "r"(ra[r] + off16), "f"(hv) : "memory");
        } else {
            g_hs[(long long)(bglob * TT + t) * HH + jglob] = hv;
        }
        asm volatile("barrier.cluster.arrive.aligned;" ::: "memory");
        asm volatile("barrier.cluster.wait.aligned;" ::: "memory");
    }
}

// ---------------- host launch ----------------
extern "C" void kernel_launch(void* const* d_in, const int* in_sizes, int n_in,
                              void* d_out, int out_size) {
    const float* enc         = (const float*)d_in[0];
    const int*   sep_mask    = (const int*)d_in[1];
    const int*   pos_ids     = (const int*)d_in[2];
    const int*   length      = (const int*)d_in[3];
    const float* pos_emb     = (const float*)d_in[4];
    const float* wordlen_emb = (const float*)d_in[5];
    const float* fc_W        = (const float*)d_in[6];
    const float* fc_b        = (const float*)d_in[7];
    const float* W_ih        = (const float*)d_in[8];
    const float* W_hh        = (const float*)d_in[9];
    const float* b_ih        = (const float*)d_in[10];
    const float* b_hh        = (const float*)d_in[11];
    const float* combine_W   = (const float*)d_in[12];
    float* out = (float*)d_out;

    float* d_feats; cudaGetSymbolAddress((void**)&d_feats, g_feats);
    float* d_fcW;   cudaGetSymbolAddress((void**)&d_fcW, g_fcW);
    float* d_Wih;   cudaGetSymbolAddress((void**)&d_Wih, g_Wih);
    float* d_z;     cudaGetSymbolAddress((void**)&d_z, g_z);
    float* d_G0;    cudaGetSymbolAddress((void**)&d_G0, g_G0);
    float* d_hs;    cudaGetSymbolAddress((void**)&d_hs, g_hs);

    // launch 1: csum + lastsep + weight padding
    prep_k<<<520, 128>>>(enc, sep_mask, fc_W, W_ih);

    // launch 2: features (massively parallel)
    feats_k<<<BB * TT, 128>>>(pos_ids, pos_emb, wordlen_emb);

    // launch 3: GEMM1  z = tanh(feats @ g_fcW^T + fc_b)   M=65536 N=200 K=592
    gemm_k<1, true><<<dim3(4, 512), 128>>>(
        d_feats, d_fcW, fc_b, nullptr, nullptr, nullptr, d_z,
        LIN, FPAD, FPAD, FPAD, LPAD, LPAD);

    // launch 4 (ncu capture slot): GEMM2  G0 = z @ g_Wih^T + biases  N=1024 K=208
    gemm_k<2, true><<<dim3(16, 512), 128>>>(
        d_z, d_Wih, b_ih, b_hh, nullptr, nullptr, d_G0,
        G4, LPAD, LPAD, LPAD, G4, G4);

    // launch 5: LSTM recurrence (clusters + DSMEM h-exchange)
    const int lstm_smem = (WROWS * WSTR + 2 * HBUF) * (int)sizeof(float);
    cudaFuncSetAttribute(lstm_k, cudaFuncAttributeMaxDynamicSharedMemorySize, lstm_smem);
    lstm_k<<<128, 512, lstm_smem>>>(W_hh);

    // launch 6: GEMM3  logits = [hs|enc] @ combine_W^T + mask
    gemm_k<3, true><<<dim3(1, 512), 128>>>(
        d_hs, combine_W, nullptr, nullptr, enc, length, out,
        SP, KV, 0, KV, SP, SP);
}

// round 14
// speedup vs baseline: 1.4746x; 1.4746x over previous
#include <cuda_runtime.h>
#include <cuda_bf16.h>
#include <cstdint>

// Problem dims
#define BB   128
#define TT   512
#define HH   256
#define H2   512
#define LIN  200
#define LPAD 208          // 13 k-tiles * 16
#define FEAT 582
#define FPAD 592          // 37 k-tiles * 16
#define G4   1024
#define SP   58
#define KV   768          // 256 + 512

typedef unsigned long long u64;

// ---------------- device scratch ----------------
__device__ float g_feats[BB * TT * FPAD];
__device__ float g_z    [BB * TT * LPAD];
__device__ float g_G0   [BB * TT * G4];
__device__ float g_hs   [BB * TT * HH];
__device__ float g_h    [2 * BB * HH];
__device__ float g_fcW  [LIN * FPAD];     // zero-padded fc_W
__device__ float g_Wih  [G4 * LPAD];      // zero-padded W_ih

#define NB_LSTM 128
#define GRP     32                          // blocks per barrier group
#define NBAR    513                         // barriers per launch per group
__device__ __align__(128) u64 g_cnt4[4 * 16];   // one counter per 128B

__device__ __forceinline__ float sigf(float x) { return 1.f / (1.f + __expf(-x)); }
__device__ __forceinline__ float tanhfast(float x) {
    float e = __expf(2.f * x);
    return 1.f - 2.f / (e + 1.f);
}

// packed fp32x2 helpers (sm_100+: fma.rn.f32x2)
__device__ __forceinline__ u64 ffma2(u64 a, u64 b, u64 c) {
    u64 d; asm("fma.rn.f32x2 %0, %1, %2, %3;" : "=l"(d) : "l"(a), "l"(b), "l"(c)); return d;
}
__device__ __forceinline__ u64 pack2(float lo, float hi) {
    u64 d; asm("mov.b64 %0, {%1, %2};" : "=l"(d) : "f"(lo), "f"(hi)); return d;
}
__device__ __forceinline__ float2 unpack2(u64 v) {
    float lo, hi; asm("mov.b64 {%0, %1}, %2;" : "=f"(lo), "=f"(hi) : "l"(v));
    return make_float2(lo, hi);
}

// ---------------- kernel 1: features by direct summation + weight padding ----
// Block m = b*T + t computes its own last-sep (backward scan, E[iters]~2) and
// the word mean by summing enc rows [ls, t) directly — no csum pass needed.
// 8 extra blocks pad fc_W / W_ih.
__global__ void __launch_bounds__(128) feats_k(
    const float* __restrict__ enc, const int* __restrict__ sep,
    const int* __restrict__ pos_ids, const float* __restrict__ pos_emb,
    const float* __restrict__ wl_emb, const float* __restrict__ fcW,
    const float* __restrict__ Wih)
{
    const int m = blockIdx.x;
    const int tid = threadIdx.x;
    if (m >= BB * TT) {
        const int gt = (m - BB * TT) * 128 + tid;   // 0..1023
        for (int i = gt; i < LIN * FPAD; i += 1024) {
            const int n = i / FPAD, k = i - n * FPAD;
            g_fcW[i] = (k < FEAT) ? fcW[n * FEAT + k] : 0.f;
        }
        for (int i = gt; i < G4 * LPAD; i += 1024) {
            const int n = i / LPAD, k = i - n * LPAD;
            g_Wih[i] = (k < LIN) ? Wih[n * LIN + k] : 0.f;
        }
        return;
    }
    const int b = m >> 9;
    const int t = m & (TT - 1);
    // last sep strictly before t (sep[b][0] == 1 always)
    int ls = 0;
    const int* sp = sep + b * TT;
    for (int k = t - 1; k >= 1; k--) {
        if (sp[k] > 0) { ls = k; break; }
    }
    int wlen = t - ls; if (wlen < 1) wlen = 1;
    const int wid = (wlen < 7) ? wlen : 7;
    const int lp = pos_ids[b * TT + ls];
    const float inv = 1.0f / (float)wlen;
    float* f = g_feats + (long long)m * FPAD;

    // word mean: sum enc rows [ls, t) directly (empty range at t==0 -> 0)
    float acc0 = 0.f, acc1 = 0.f, acc2 = 0.f, acc3 = 0.f;
    const float* e = enc + ((long long)b * TT + ls) * H2;
    for (int k = ls; k < t; k++, e += H2) {
        acc0 += e[tid];
        acc1 += e[tid + 128];
        acc2 += e[tid + 256];
        acc3 += e[tid + 384];
    }
    f[50 + tid      ] = acc0 * inv;
    f[50 + tid + 128] = acc1 * inv;
    f[50 + tid + 256] = acc2 * inv;
    f[50 + tid + 384] = acc3 * inv;

    // head / tail / padding
    for (int i = tid; i < FPAD; i += 128) {
        if (i < 50)        f[i] = pos_emb[lp * 50 + i];
        else if (i >= 582) f[i] = 0.f;
        else if (i >= 562) f[i] = wl_emb[wid * 20 + (i - 562)];
    }
}

// ---------------- fp32 GEMM with FFMA2: C[M,N] = A[M,K] * B[N,K]^T ----------
// BM=128, BN=64, BK=16, 128 threads, 8x8 microtile (pairs along m).
template<int MODE, bool KMUL16>
__global__ void __launch_bounds__(128) gemm_k(
    const float* __restrict__ A, const float* __restrict__ Bm,
    const float* __restrict__ bias1, const float* __restrict__ bias2,
    const float* __restrict__ enc, const int* __restrict__ length,
    float* __restrict__ C, int N, int K, int lda, int ldb, int ldc, int nstore)
{
    __shared__ __align__(16) float Asm[16][132];
    __shared__ __align__(16) float Bsm[16][72];
    const int n0 = blockIdx.x * 64;
    const int m0 = blockIdx.y * 128;
    const int tid = threadIdx.x;
    const int tx = tid & 7, ty = tid >> 3;

    const int arow = tid >> 2;          // 0..31
    const int akq  = (tid & 3) * 4;     // 0,4,8,12
    const int brow = tid >> 1;          // 0..63
    const int bk0  = (tid & 1) * 8;     // 0 or 8

    u64 acc[4][8];
    #pragma unroll
    for (int p = 0; p < 4; p++)
        #pragma unroll
        for (int q = 0; q < 8; q++) acc[p][q] = 0ull;

    float bsum[8];
    #pragma unroll
    for (int q = 0; q < 8; q++) {
        const int n = n0 + tx * 8 + q;
        if (MODE == 1)      bsum[q] = (n < N) ? bias1[n] : 0.f;
        else if (MODE == 2) bsum[q] = bias1[n] + bias2[n];
        else                bsum[q] = 0.f;
    }

    const int nkt = (K + 15) >> 4;

    float4 ra[4], rb[2], na[4], nb[2];

    auto loadA = [&](int kt, float4* r) {
        const int k = kt * 16 + akq;
        #pragma unroll
        for (int p = 0; p < 4; p++) {
            const int m = m0 + arow + p * 32;
            if (MODE == 3) {
                const float* src = (k < 256) ? (A + (long long)m * 256 + k)
                                             : (enc + (long long)m * 512 + (k - 256));
                r[p] = *reinterpret_cast<const float4*>(src);
            } else {
                r[p] = *reinterpret_cast<const float4*>(A + (long long)m * lda + k);
            }
        }
    };
    auto loadB = [&](int kt, float4* r) {
        const int n = n0 + brow;
        #pragma unroll
        for (int q = 0; q < 2; q++) {
            const int k = kt * 16 + bk0 + q * 4;
            float4 v = make_float4(0.f, 0.f, 0.f, 0.f);
            if (n < N) {
                if (KMUL16 || k + 3 < K) {
                    v = *reinterpret_cast<const float4*>(Bm + (long long)n * ldb + k);
                } else {
                    float t4[4];
                    #pragma unroll
                    for (int i = 0; i < 4; i++)
                        t4[i] = (k + i < K) ? Bm[(long long)n * ldb + k + i] : 0.f;
                    v = make_float4(t4[0], t4[1], t4[2], t4[3]);
                }
            }
            r[q] = v;
        }
    };

    loadA(0, ra); loadB(0, rb);
    for (int kt = 0; kt < nkt; kt++) {
        #pragma unroll
        for (int p = 0; p < 4; p++) {
            Asm[akq + 0][arow + p * 32] = ra[p].x;
            Asm[akq + 1][arow + p * 32] = ra[p].y;
            Asm[akq + 2][arow + p * 32] = ra[p].z;
            Asm[akq + 3][arow + p * 32] = ra[p].w;
        }
        #pragma unroll
        for (int q = 0; q < 2; q++) {
            Bsm[bk0 + q * 4 + 0][brow] = rb[q].x;
            Bsm[bk0 + q * 4 + 1][brow] = rb[q].y;
            Bsm[bk0 + q * 4 + 2][brow] = rb[q].z;
            Bsm[bk0 + q * 4 + 3][brow] = rb[q].w;
        }
        __syncthreads();
        if (kt + 1 < nkt) { loadA(kt + 1, na); loadB(kt + 1, nb); }
        #pragma unroll
        for (int kk = 0; kk < 16; kk++) {
            const ulonglong2 a01 = *reinterpret_cast<const ulonglong2*>(&Asm[kk][ty * 8]);
            const ulonglong2 a23 = *reinterpret_cast<const ulonglong2*>(&Asm[kk][ty * 8 + 4]);
            const float4 b0 = *reinterpret_cast<const float4*>(&Bsm[kk][tx * 8]);
            const float4 b1 = *reinterpret_cast<const float4*>(&Bsm[kk][tx * 8 + 4]);
            u64 av[4] = {a01.x, a01.y, a23.x, a23.y};
            u64 bd[8] = {pack2(b0.x, b0.x), pack2(b0.y, b0.y), pack2(b0.z, b0.z), pack2(b0.w, b0.w),
                         pack2(b1.x, b1.x), pack2(b1.y, b1.y), pack2(b1.z, b1.z), pack2(b1.w, b1.w)};
            #pragma unroll
            for (int p = 0; p < 4; p++)
                #pragma unroll
                for (int q = 0; q < 8; q++)
                    acc[p][q] = ffma2(av[p], bd[q], acc[p][q]);
        }
        __syncthreads();
        #pragma unroll
        for (int p = 0; p < 4; p++) ra[p] = na[p];
        rb[0] = nb[0]; rb[1] = nb[1];
    }

    const bool vec = (MODE == 2) || (MODE == 1 && n0 + 64 <= N);
    #pragma unroll
    for (int p = 0; p < 4; p++) {
        float2 fr[8];
        #pragma unroll
        for (int q = 0; q < 8; q++) fr[q] = unpack2(acc[p][q]);
        #pragma unroll
        for (int half = 0; half < 2; half++) {
            const int m = m0 + ty * 8 + p * 2 + half;
            const int t = m & (TT - 1);
            float vals[8];
            int lenb = 0;
            if (MODE == 3) lenb = length[m >> 9];
            #pragma unroll
            for (int q = 0; q < 8; q++) {
                const int n = n0 + tx * 8 + q;
                float v = half ? fr[q].y : fr[q].x;
                if (MODE == 1) {
                    if (n < N) { v = tanhfast(v + bsum[q]); if (t == 0) v = 0.f; }
                    else v = 0.f;
                } else if (MODE == 2) {
                    v += bsum[q];
                } else {
                    if (t >= lenb) v = 0.f;
                    if (t == 0 && n == 0) v = -1e30f;
                }
                vals[q] = v;
            }
            float* cp = C + (long long)m * ldc + n0 + tx * 8;
            if (vec) {
                *reinterpret_cast<float4*>(cp)     = make_float4(vals[0], vals[1], vals[2], vals[3]);
                *reinterpret_cast<float4*>(cp + 4) = make_float4(vals[4], vals[5], vals[6], vals[7]);
            } else {
                #pragma unroll
                for (int q = 0; q < 8; q++) {
                    const int n = n0 + tx * 8 + q;
                    if (n < nstore) cp[q] = vals[q];
                }
            }
        }
    }
}

// ---------------- per-group grid barrier: RED arrival + single poller -------
__device__ __forceinline__ void gbar_grp(u64* cnt, u64 base, int e) {
    __threadfence();
    __syncthreads();
    if (threadIdx.x == 0) {
        atomicAdd(cnt, 1ULL);                  // result unused -> RED
        const u64 tgt = base + (u64)e * (u64)GRP;
        while (*(volatile u64*)cnt < tgt) { }
        __threadfence();
    }
    __syncthreads();
}

// ---------------- persistent LSTM recurrence (FFMA2, 512 threads) ----------
// 128 blocks: bt(0..3)*32 batches x ht(0..31)*8 hidden.
// 512 threads: thread = (bg 0..31 batch, gp 0..1 gate-pair, jj 0..7 hidden).
// gp=0 handles gates (i,f); gp=1 handles (g,o); recombine via shfl.xor(8).
// g_hs stores are deferred one step so they drain before the barrier fence.
__global__ void __launch_bounds__(512, 1) lstm_k(const float* __restrict__ W_hh) {
    extern __shared__ float sm[];
    float* Wsm = sm;                 // [32][260] rows: gate*8 + jj
    float* Hsm = sm + 32 * 260;      // [32][260] rows: batch-in-tile
    __shared__ u64 s_base;
    const int bt = blockIdx.x >> 5;
    const int ht = blockIdx.x & 31;
    const int tid = threadIdx.x;
    const int bg = tid >> 4;             // 0..31
    const int gp = (tid >> 3) & 1;       // 0..1
    const int jj = tid & 7;              // 0..7
    const int b = bt * 32 + bg;
    const int j = ht * 8 + jj;
    u64* cnt = &g_cnt4[bt * 16];

    if (tid == 0) {
        const u64 c0 = *(volatile u64*)cnt;
        s_base = c0 - (c0 % (u64)(NBAR * GRP));
    }
    // cache W slice: smem row r = gate(r>>3)*8 + hidden(r&7)
    #pragma unroll
    for (int i = 0; i < 4; i++) {
        const int idx = tid + i * 512;
        const int r = idx >> 6, k4 = idx & 63;
        const int g = r >> 3, hr = r & 7;
        const float4 w = reinterpret_cast<const float4*>(W_hh)[(g * 256 + ht * 8 + hr) * 64 + k4];
        *reinterpret_cast<float4*>(&Wsm[r * 260 + k4 * 4]) = w;
    }
    if (gp == 0) g_h[b * HH + j] = 0.f;
    float c = 0.f;
    float hs_pend = 0.f;

    // prefetch G0 for t=0: this thread's 2 gates (2gp, 2gp+1)
    float pg0, pg1;
    {
        const float* G = g_G0 + (long long)(b * TT) * G4 + j + gp * 512;
        pg0 = G[0]; pg1 = G[256];
    }
    __syncthreads();
    const u64 base = s_base;
    gbar_grp(cnt, base, 1);

    const float* Wr0 = &Wsm[(gp * 16 + jj) * 260];        // gate 2gp
    const float* Wr1 = Wr0 + 8 * 260;                      // gate 2gp+1
    const float* Hr  = &Hsm[bg * 260];

    for (int t = 0; t < TT; t++) {
        // deferred hs store from previous step (has all of this step to drain)
        if (gp && t > 0) g_hs[(long long)(b * TT + t - 1) * HH + j] = hs_pend;
        // stage h tile [32 x 256] into smem
        const float* hb = g_h + (t & 1) * (BB * HH) + bt * 32 * HH;
        #pragma unroll
        for (int i = 0; i < 4; i++) {
            const int idx = tid + i * 512;
            const int r = idx >> 6, k4 = idx & 63;
            *reinterpret_cast<float4*>(&Hsm[r * 260 + k4 * 4]) =
                reinterpret_cast<const float4*>(hb)[r * 64 + k4];
        }
        u64 acc0 = pack2(pg0, 0.f);
        u64 acc1 = pack2(pg1, 0.f);
        if (t + 1 < TT) {
            const float* G = g_G0 + (long long)(b * TT + t + 1) * G4 + j + gp * 512;
            pg0 = G[0]; pg1 = G[256];
        }
        __syncthreads();

        #pragma unroll 16
        for (int k4 = 0; k4 < 64; k4++) {
            const ulonglong2 h2 = *reinterpret_cast<const ulonglong2*>(Hr + k4 * 4);
            ulonglong2 w;
            w = *reinterpret_cast<const ulonglong2*>(Wr0 + k4 * 4);
            acc0 = ffma2(h2.x, w.x, acc0); acc0 = ffma2(h2.y, w.y, acc0);
            w = *reinterpret_cast<const ulonglong2*>(Wr1 + k4 * 4);
            acc1 = ffma2(h2.x, w.x, acc1); acc1 = ffma2(h2.y, w.y, acc1);
        }
        const float2 f0 = unpack2(acc0);
        const float2 f1 = unpack2(acc1);
        const float s0 = f0.x + f0.y;          // gp0: i-sum   gp1: g-sum
        const float s1 = f1.x + f1.y;          // gp0: f-sum   gp1: o-sum
        // branchless: sig(x) = 0.5*tanh(x/2)+0.5
        const float scl = gp ? 1.0f : 0.5f;
        const float off = gp ? 0.0f : 0.5f;
        const float a0 = tanhfast(s0 * scl) * scl + off;   // gp0: sig(i)  gp1: tanh(g)
        const float a1 = sigf(s1);                          // gp0: sig(f)  gp1: sig(o)
        const float e0 = __shfl_xor_sync(0xffffffffu, a0, 8);
        const float e1 = __shfl_xor_sync(0xffffffffu, a1, 8);
        const float si = gp ? e0 : a0;
        const float sf = gp ? e1 : a1;
        const float tg = gp ? a0 : e0;
        const float so = gp ? a1 : e1;
        c = sf * c + si * tg;
        const float hv = so * tanhfast(c);

        if (gp) hs_pend = hv;   // store next iteration (off the fence path)
        else    g_h[((t + 1) & 1) * (BB * HH) + b * HH + j] = hv;
        gbar_grp(cnt, base, 2 + t);
    }
    if (gp) g_hs[(long long)(b * TT + TT - 1) * HH + j] = hs_pend;
}

// ---------------- host launch ----------------
extern "C" void kernel_launch(void* const* d_in, const int* in_sizes, int n_in,
                              void* d_out, int out_size) {
    const float* enc         = (const float*)d_in[0];
    const int*   sep_mask    = (const int*)d_in[1];
    const int*   pos_ids     = (const int*)d_in[2];
    const int*   length      = (const int*)d_in[3];
    const float* pos_emb     = (const float*)d_in[4];
    const float* wordlen_emb = (const float*)d_in[5];
    const float* fc_W        = (const float*)d_in[6];
    const float* fc_b        = (const float*)d_in[7];
    const float* W_ih        = (const float*)d_in[8];
    const float* W_hh        = (const float*)d_in[9];
    const float* b_ih        = (const float*)d_in[10];
    const float* b_hh        = (const float*)d_in[11];
    const float* combine_W   = (const float*)d_in[12];
    float* out = (float*)d_out;

    float* d_feats; cudaGetSymbolAddress((void**)&d_feats, g_feats);
    float* d_fcW;   cudaGetSymbolAddress((void**)&d_fcW, g_fcW);
    float* d_Wih;   cudaGetSymbolAddress((void**)&d_Wih, g_Wih);
    float* d_z;     cudaGetSymbolAddress((void**)&d_z, g_z);
    float* d_G0;    cudaGetSymbolAddress((void**)&d_G0, g_G0);
    float* d_hs;    cudaGetSymbolAddress((void**)&d_hs, g_hs);

    // launch 1: features (direct word-mean, no csum) + weight padding
    feats_k<<<BB * TT + 8, 128>>>(enc, sep_mask, pos_ids, pos_emb,
                                  wordlen_emb, fc_W, W_ih);

    // launch 2: GEMM1  z = tanh(feats @ g_fcW^T + fc_b)   M=65536 N=200 K=592
    gemm_k<1, true><<<dim3(4, 512), 128>>>(
        d_feats, d_fcW, fc_b, nullptr, nullptr, nullptr, d_z,
        LIN, FPAD, FPAD, FPAD, LPAD, LPAD);

    // launch 3: GEMM2  G0 = z @ g_Wih^T + b_ih + b_hh     M=65536 N=1024 K=208
    gemm_k<2, true><<<dim3(16, 512), 128>>>(
        d_z, d_Wih, b_ih, b_hh, nullptr, nullptr, d_G0,
        G4, LPAD, LPAD, LPAD, G4, G4);

    // launch 4 (ncu capture slot): LSTM recurrence (persistent, RED barriers)
    const int lstm_smem = 2 * 32 * 260 * (int)sizeof(float);
    cudaFuncSetAttribute(lstm_k, cudaFuncAttributeMaxDynamicSharedMemorySize, lstm_smem);
    lstm_k<<<NB_LSTM, 512, lstm_smem>>>(W_hh);

    // launch 5: GEMM3  logits = [hs|enc] @ combine_W^T + mask
    gemm_k<3, true><<<dim3(1, 512), 128>>>(
        d_hs, combine_W, nullptr, nullptr, enc, length, out,
        SP, KV, 0, KV, SP, SP);
}

// round 15
// speedup vs baseline: 1.7488x; 1.1859x over previous
#include <cuda_runtime.h>
#include <cuda_bf16.h>
#include <cstdint>

// Problem dims
#define BB   128
#define TT   512
#define HH   256
#define H2   512
#define LIN  200
#define LPAD 208          // 13 k-tiles * 16
#define FEAT 582
#define FPAD 592          // 37 k-tiles * 16
#define G4   1024
#define SP   58
#define KV   768          // 256 + 512

typedef unsigned long long u64;

// ---------------- device scratch ----------------
__device__ float g_feats[BB * TT * FPAD];
__device__ float g_z    [BB * TT * LPAD];
__device__ float g_G0   [BB * TT * G4];
__device__ float g_hs   [BB * TT * HH];
__device__ float g_h    [2 * BB * HH];
__device__ float g_fcW  [LIN * FPAD];     // zero-padded fc_W
__device__ float g_Wih  [G4 * LPAD];      // zero-padded W_ih

#define NB_LSTM 128
#define GRP     32                          // blocks per barrier group
#define NBAR    513                         // barriers per launch per group
__device__ __align__(128) u64 g_cnt4[4 * 16];   // one counter per 128B

__device__ __forceinline__ float sigf(float x) { return 1.f / (1.f + __expf(-x)); }
__device__ __forceinline__ float tanhfast(float x) {
    float e = __expf(2.f * x);
    return 1.f - 2.f / (e + 1.f);
}

// packed fp32x2 helpers (sm_100+: fma.rn.f32x2)
__device__ __forceinline__ u64 ffma2(u64 a, u64 b, u64 c) {
    u64 d; asm("fma.rn.f32x2 %0, %1, %2, %3;" : "=l"(d) : "l"(a), "l"(b), "l"(c)); return d;
}
__device__ __forceinline__ u64 pack2(float lo, float hi) {
    u64 d; asm("mov.b64 %0, {%1, %2};" : "=l"(d) : "f"(lo), "f"(hi)); return d;
}
__device__ __forceinline__ float2 unpack2(u64 v) {
    float lo, hi; asm("mov.b64 {%0, %1}, %2;" : "=f"(lo), "=f"(hi) : "l"(v));
    return make_float2(lo, hi);
}

// ---------------- kernel 1: features by direct summation + weight padding ----
__global__ void __launch_bounds__(128) feats_k(
    const float* __restrict__ enc, const int* __restrict__ sep,
    const int* __restrict__ pos_ids, const float* __restrict__ pos_emb,
    const float* __restrict__ wl_emb, const float* __restrict__ fcW,
    const float* __restrict__ Wih)
{
    const int m = blockIdx.x;
    const int tid = threadIdx.x;
    if (m >= BB * TT) {
        const int gt = (m - BB * TT) * 128 + tid;   // 0..1023
        for (int i = gt; i < LIN * FPAD; i += 1024) {
            const int n = i / FPAD, k = i - n * FPAD;
            g_fcW[i] = (k < FEAT) ? fcW[n * FEAT + k] : 0.f;
        }
        for (int i = gt; i < G4 * LPAD; i += 1024) {
            const int n = i / LPAD, k = i - n * LPAD;
            g_Wih[i] = (k < LIN) ? Wih[n * LIN + k] : 0.f;
        }
        return;
    }
    const int b = m >> 9;
    const int t = m & (TT - 1);
    int ls = 0;
    const int* sp = sep + b * TT;
    for (int k = t - 1; k >= 1; k--) {
        if (sp[k] > 0) { ls = k; break; }
    }
    int wlen = t - ls; if (wlen < 1) wlen = 1;
    const int wid = (wlen < 7) ? wlen : 7;
    const int lp = pos_ids[b * TT + ls];
    const float inv = 1.0f / (float)wlen;
    float* f = g_feats + (long long)m * FPAD;

    float acc0 = 0.f, acc1 = 0.f, acc2 = 0.f, acc3 = 0.f;
    const float* e = enc + ((long long)b * TT + ls) * H2;
    for (int k = ls; k < t; k++, e += H2) {
        acc0 += e[tid];
        acc1 += e[tid + 128];
        acc2 += e[tid + 256];
        acc3 += e[tid + 384];
    }
    f[50 + tid      ] = acc0 * inv;
    f[50 + tid + 128] = acc1 * inv;
    f[50 + tid + 256] = acc2 * inv;
    f[50 + tid + 384] = acc3 * inv;

    for (int i = tid; i < FPAD; i += 128) {
        if (i < 50)        f[i] = pos_emb[lp * 50 + i];
        else if (i >= 582) f[i] = 0.f;
        else if (i >= 562) f[i] = wl_emb[wid * 20 + (i - 562)];
    }
}

// ---------------- fp32 GEMM with FFMA2: C[M,N] = A[M,K] * B[N,K]^T ----------
template<int MODE, bool KMUL16>
__global__ void __launch_bounds__(128) gemm_k(
    const float* __restrict__ A, const float* __restrict__ Bm,
    const float* __restrict__ bias1, const float* __restrict__ bias2,
    const float* __restrict__ enc, const int* __restrict__ length,
    float* __restrict__ C, int N, int K, int lda, int ldb, int ldc, int nstore)
{
    __shared__ __align__(16) float Asm[16][132];
    __shared__ __align__(16) float Bsm[16][72];
    const int n0 = blockIdx.x * 64;
    const int m0 = blockIdx.y * 128;
    const int tid = threadIdx.x;
    const int tx = tid & 7, ty = tid >> 3;

    const int arow = tid >> 2;
    const int akq  = (tid & 3) * 4;
    const int brow = tid >> 1;
    const int bk0  = (tid & 1) * 8;

    u64 acc[4][8];
    #pragma unroll
    for (int p = 0; p < 4; p++)
        #pragma unroll
        for (int q = 0; q < 8; q++) acc[p][q] = 0ull;

    float bsum[8];
    #pragma unroll
    for (int q = 0; q < 8; q++) {
        const int n = n0 + tx * 8 + q;
        if (MODE == 1)      bsum[q] = (n < N) ? bias1[n] : 0.f;
        else if (MODE == 2) bsum[q] = bias1[n] + bias2[n];
        else                bsum[q] = 0.f;
    }

    const int nkt = (K + 15) >> 4;

    float4 ra[4], rb[2], na[4], nb[2];

    auto loadA = [&](int kt, float4* r) {
        const int k = kt * 16 + akq;
        #pragma unroll
        for (int p = 0; p < 4; p++) {
            const int m = m0 + arow + p * 32;
            if (MODE == 3) {
                const float* src = (k < 256) ? (A + (long long)m * 256 + k)
                                             : (enc + (long long)m * 512 + (k - 256));
                r[p] = *reinterpret_cast<const float4*>(src);
            } else {
                r[p] = *reinterpret_cast<const float4*>(A + (long long)m * lda + k);
            }
        }
    };
    auto loadB = [&](int kt, float4* r) {
        const int n = n0 + brow;
        #pragma unroll
        for (int q = 0; q < 2; q++) {
            const int k = kt * 16 + bk0 + q * 4;
            float4 v = make_float4(0.f, 0.f, 0.f, 0.f);
            if (n < N) {
                if (KMUL16 || k + 3 < K) {
                    v = *reinterpret_cast<const float4*>(Bm + (long long)n * ldb + k);
                } else {
                    float t4[4];
                    #pragma unroll
                    for (int i = 0; i < 4; i++)
                        t4[i] = (k + i < K) ? Bm[(long long)n * ldb + k + i] : 0.f;
                    v = make_float4(t4[0], t4[1], t4[2], t4[3]);
                }
            }
            r[q] = v;
        }
    };

    loadA(0, ra); loadB(0, rb);
    for (int kt = 0; kt < nkt; kt++) {
        #pragma unroll
        for (int p = 0; p < 4; p++) {
            Asm[akq + 0][arow + p * 32] = ra[p].x;
            Asm[akq + 1][arow + p * 32] = ra[p].y;
            Asm[akq + 2][arow + p * 32] = ra[p].z;
            Asm[akq + 3][arow + p * 32] = ra[p].w;
        }
        #pragma unroll
        for (int q = 0; q < 2; q++) {
            Bsm[bk0 + q * 4 + 0][brow] = rb[q].x;
            Bsm[bk0 + q * 4 + 1][brow] = rb[q].y;
            Bsm[bk0 + q * 4 + 2][brow] = rb[q].z;
            Bsm[bk0 + q * 4 + 3][brow] = rb[q].w;
        }
        __syncthreads();
        if (kt + 1 < nkt) { loadA(kt + 1, na); loadB(kt + 1, nb); }
        #pragma unroll
        for (int kk = 0; kk < 16; kk++) {
            const ulonglong2 a01 = *reinterpret_cast<const ulonglong2*>(&Asm[kk][ty * 8]);
            const ulonglong2 a23 = *reinterpret_cast<const ulonglong2*>(&Asm[kk][ty * 8 + 4]);
            const float4 b0 = *reinterpret_cast<const float4*>(&Bsm[kk][tx * 8]);
            const float4 b1 = *reinterpret_cast<const float4*>(&Bsm[kk][tx * 8 + 4]);
            u64 av[4] = {a01.x, a01.y, a23.x, a23.y};
            u64 bd[8] = {pack2(b0.x, b0.x), pack2(b0.y, b0.y), pack2(b0.z, b0.z), pack2(b0.w, b0.w),
                         pack2(b1.x, b1.x), pack2(b1.y, b1.y), pack2(b1.z, b1.z), pack2(b1.w, b1.w)};
            #pragma unroll
            for (int p = 0; p < 4; p++)
                #pragma unroll
                for (int q = 0; q < 8; q++)
                    acc[p][q] = ffma2(av[p], bd[q], acc[p][q]);
        }
        __syncthreads();
        #pragma unroll
        for (int p = 0; p < 4; p++) ra[p] = na[p];
        rb[0] = nb[0]; rb[1] = nb[1];
    }

    const bool vec = (MODE == 2) || (MODE == 1 && n0 + 64 <= N);
    #pragma unroll
    for (int p = 0; p < 4; p++) {
        float2 fr[8];
        #pragma unroll
        for (int q = 0; q < 8; q++) fr[q] = unpack2(acc[p][q]);
        #pragma unroll
        for (int half = 0; half < 2; half++) {
            const int m = m0 + ty * 8 + p * 2 + half;
            const int t = m & (TT - 1);
            float vals[8];
            int lenb = 0;
            if (MODE == 3) lenb = length[m >> 9];
            #pragma unroll
            for (int q = 0; q < 8; q++) {
                const int n = n0 + tx * 8 + q;
                float v = half ? fr[q].y : fr[q].x;
                if (MODE == 1) {
                    if (n < N) { v = tanhfast(v + bsum[q]); if (t == 0) v = 0.f; }
                    else v = 0.f;
                } else if (MODE == 2) {
                    v += bsum[q];
                } else {
                    if (t >= lenb) v = 0.f;
                    if (t == 0 && n == 0) v = -1e30f;
                }
                vals[q] = v;
            }
            float* cp = C + (long long)m * ldc + n0 + tx * 8;
            if (vec) {
                *reinterpret_cast<float4*>(cp)     = make_float4(vals[0], vals[1], vals[2], vals[3]);
                *reinterpret_cast<float4*>(cp + 4) = make_float4(vals[4], vals[5], vals[6], vals[7]);
            } else {
                #pragma unroll
                for (int q = 0; q < 8; q++) {
                    const int n = n0 + tx * 8 + q;
                    if (n < nstore) cp[q] = vals[q];
                }
            }
        }
    }
}

// ---------------- per-group grid barrier: RED arrival + single poller -------
__device__ __forceinline__ void gbar_grp(u64* cnt, u64 base, int e) {
    __threadfence();
    __syncthreads();
    if (threadIdx.x == 0) {
        atomicAdd(cnt, 1ULL);                  // result unused -> RED
        const u64 tgt = base + (u64)e * (u64)GRP;
        while (*(volatile u64*)cnt < tgt) { }
        __threadfence();
    }
    __syncthreads();
}

// ---------------- persistent LSTM recurrence: 4x4 register blocking ---------
// 128 blocks: bt(0..3)*32 batches x ht(0..31)*8 hidden.
// 256 threads: tid = kc*64 + bq*8 + rq.
//   kc 0..3 : k-slice [kc*64, kc*64+64)
//   bq 0..7 : batches {bq, bq+8, bq+16, bq+24} within the 32-batch tile
//   rq 0..7 : hidden unit j = ht*8 + rq, all 4 gates (W rows rq + 8g)
// Row choices {x, x+8, x+16, x+24} with stride 260 make every LDS.128
// conflict-free (bank delta 4/row -> 8 distinct bank-quads per warp).
// k-partials reduced via smem; kc==0 threads run the cell update.
#define RSTR 20                               // RED slot stride (floats)
__global__ void __launch_bounds__(256, 1) lstm_k(const float* __restrict__ W_hh) {
    extern __shared__ float sm[];
    float* Wsm = sm;                          // [32][260] row = g*8 + hr
    float* Hsm = sm + 32 * 260;               // [32][260] row = batch-in-tile
    float* RED = sm + 64 * 260;               // [3][64][RSTR]
    __shared__ u64 s_base;
    const int bt = blockIdx.x >> 5;
    const int ht = blockIdx.x & 31;
    const int tid = threadIdx.x;
    const int kc = tid >> 6;                  // 0..3
    const int bq = (tid >> 3) & 7;            // 0..7
    const int rq = tid & 7;                   // 0..7
    const int slot = bq * 8 + rq;             // 0..63
    const int j = ht * 8 + rq;
    u64* cnt = &g_cnt4[bt * 16];

    if (tid == 0) {
        const u64 c0 = *(volatile u64*)cnt;
        s_base = c0 - (c0 % (u64)(NBAR * GRP));
    }
    // stage W slice: smem row r = g*8 + hr  <-  W_hh[g*256 + ht*8 + hr]
    #pragma unroll
    for (int i = 0; i < 8; i++) {
        const int idx = tid + i * 256;
        const int r = idx >> 6, k4 = idx & 63;
        const int g = r >> 3, hr = r & 7;
        const float4 w = reinterpret_cast<const float4*>(W_hh)[(g * 256 + ht * 8 + hr) * 64 + k4];
        *reinterpret_cast<float4*>(&Wsm[r * 260 + k4 * 4]) = w;
    }

    int bglob[4];
    #pragma unroll
    for (int i = 0; i < 4; i++) bglob[i] = bt * 32 + bq + 8 * i;
    float cst[4] = {0.f, 0.f, 0.f, 0.f};
    if (kc == 0) {
        #pragma unroll
        for (int i = 0; i < 4; i++) g_h[bglob[i] * HH + j] = 0.f;
    }
    __syncthreads();
    const u64 base = s_base;
    gbar_grp(cnt, base, 1);

    const float* Wb = Wsm + rq * 260 + kc * 64;   // gate g at +g*2080
    const float* Hb = Hsm + bq * 260 + kc * 64;   // batch i at +i*2080

    for (int t = 0; t < TT; t++) {
        // stage h tile [32 x 256] into smem
        const float* hb = g_h + (t & 1) * (BB * HH) + bt * 32 * HH;
        #pragma unroll
        for (int i = 0; i < 8; i++) {
            const int idx = tid + i * 256;
            const int r = idx >> 6, k4 = idx & 63;
            *reinterpret_cast<float4*>(&Hsm[r * 260 + k4 * 4]) =
                reinterpret_cast<const float4*>(hb)[r * 64 + k4];
        }
        // G0 for this step (kc0 only; ~2000 cycles to drain before use)
        float pg[4][4];
        if (kc == 0) {
            #pragma unroll
            for (int i = 0; i < 4; i++) {
                const float* G = g_G0 + (long long)(bglob[i] * TT + t) * G4 + j;
                #pragma unroll
                for (int g = 0; g < 4; g++) pg[i][g] = G[g * 256];
            }
        }
        __syncthreads();

        u64 acc[4][4];
        #pragma unroll
        for (int i = 0; i < 4; i++)
            #pragma unroll
            for (int g = 0; g < 4; g++) acc[i][g] = 0ull;

        #pragma unroll 4
        for (int k4 = 0; k4 < 16; k4++) {
            ulonglong2 h[4], w[4];
            #pragma unroll
            for (int i = 0; i < 4; i++)
                h[i] = *reinterpret_cast<const ulonglong2*>(Hb + i * 2080 + k4 * 4);
            #pragma unroll
            for (int g = 0; g < 4; g++)
                w[g] = *reinterpret_cast<const ulonglong2*>(Wb + g * 2080 + k4 * 4);
            #pragma unroll
            for (int i = 0; i < 4; i++)
                #pragma unroll
                for (int g = 0; g < 4; g++) {
                    acc[i][g] = ffma2(h[i].x, w[g].x, acc[i][g]);
                    acc[i][g] = ffma2(h[i].y, w[g].y, acc[i][g]);
                }
        }
        // fold packed lanes
        float s[4][4];
        #pragma unroll
        for (int i = 0; i < 4; i++)
            #pragma unroll
            for (int g = 0; g < 4; g++) {
                const float2 f = unpack2(acc[i][g]);
                s[i][g] = f.x + f.y;
            }
        if (kc) {
            float* rp = RED + (kc - 1) * 64 * RSTR + slot * RSTR;
            #pragma unroll
            for (int i = 0; i < 4; i++)
                *reinterpret_cast<float4*>(&rp[i * 4]) =
                    make_float4(s[i][0], s[i][1], s[i][2], s[i][3]);
        }
        __syncthreads();
        if (kc == 0) {
            #pragma unroll
            for (int p = 0; p < 3; p++) {
                const float* rp = RED + p * 64 * RSTR + slot * RSTR;
                #pragma unroll
                for (int i = 0; i < 4; i++) {
                    const float4 v = *reinterpret_cast<const float4*>(&rp[i * 4]);
                    s[i][0] += v.x; s[i][1] += v.y; s[i][2] += v.z; s[i][3] += v.w;
                }
            }
            float* hn = g_h + ((t + 1) & 1) * (BB * HH);
            #pragma unroll
            for (int i = 0; i < 4; i++) {
                const float gi = sigf(s[i][0] + pg[i][0]);
                const float gf = sigf(s[i][1] + pg[i][1]);
                const float gg = tanhfast(s[i][2] + pg[i][2]);
                const float go = sigf(s[i][3] + pg[i][3]);
                cst[i] = gf * cst[i] + gi * gg;
                const float hv = go * tanhfast(cst[i]);
                hn[bglob[i] * HH + j] = hv;
                g_hs[(long long)(bglob[i] * TT + t) * HH + j] = hv;
            }
        }
        gbar_grp(cnt, base, 2 + t);
    }
}

// ---------------- host launch ----------------
extern "C" void kernel_launch(void* const* d_in, const int* in_sizes, int n_in,
                              void* d_out, int out_size) {
    const float* enc         = (const float*)d_in[0];
    const int*   sep_mask    = (const int*)d_in[1];
    const int*   pos_ids     = (const int*)d_in[2];
    const int*   length      = (const int*)d_in[3];
    const float* pos_emb     = (const float*)d_in[4];
    const float* wordlen_emb = (const float*)d_in[5];
    const float* fc_W        = (const float*)d_in[6];
    const float* fc_b        = (const float*)d_in[7];
    const float* W_ih        = (const float*)d_in[8];
    const float* W_hh        = (const float*)d_in[9];
    const float* b_ih        = (const float*)d_in[10];
    const float* b_hh        = (const float*)d_in[11];
    const float* combine_W   = (const float*)d_in[12];
    float* out = (float*)d_out;

    float* d_feats; cudaGetSymbolAddress((void**)&d_feats, g_feats);
    float* d_fcW;   cudaGetSymbolAddress((void**)&d_fcW, g_fcW);
    float* d_Wih;   cudaGetSymbolAddress((void**)&d_Wih, g_Wih);
    float* d_z;     cudaGetSymbolAddress((void**)&d_z, g_z);
    float* d_G0;    cudaGetSymbolAddress((void**)&d_G0, g_G0);
    float* d_hs;    cudaGetSymbolAddress((void**)&d_hs, g_hs);

    // launch 1: features (direct word-mean) + weight padding
    feats_k<<<BB * TT + 8, 128>>>(enc, sep_mask, pos_ids, pos_emb,
                                  wordlen_emb, fc_W, W_ih);

    // launch 2: GEMM1  z = tanh(feats @ g_fcW^T + fc_b)   M=65536 N=200 K=592
    gemm_k<1, true><<<dim3(4, 512), 128>>>(
        d_feats, d_fcW, fc_b, nullptr, nullptr, nullptr, d_z,
        LIN, FPAD, FPAD, FPAD, LPAD, LPAD);

    // launch 3: GEMM2  G0 = z @ g_Wih^T + b_ih + b_hh     M=65536 N=1024 K=208
    gemm_k<2, true><<<dim3(16, 512), 128>>>(
        d_z, d_Wih, b_ih, b_hh, nullptr, nullptr, d_G0,
        G4, LPAD, LPAD, LPAD, G4, G4);

    // launch 4 (ncu capture slot): LSTM recurrence (4x4 register blocking)
    const int lstm_smem = (64 * 260 + 3 * 64 * RSTR) * (int)sizeof(float);
    cudaFuncSetAttribute(lstm_k, cudaFuncAttributeMaxDynamicSharedMemorySize, lstm_smem);
    lstm_k<<<NB_LSTM, 256, lstm_smem>>>(W_hh);

    // launch 5: GEMM3  logits = [hs|enc] @ combine_W^T + mask
    gemm_k<3, true><<<dim3(1, 512), 128>>>(
        d_hs, combine_W, nullptr, nullptr, enc, length, out,
        SP, KV, 0, KV, SP, SP);
}

// round 16
// speedup vs baseline: 2.2507x; 1.2870x over previous
#include <cuda_runtime.h>
#include <cuda_bf16.h>
#include <cstdint>

// Problem dims
#define BB   128
#define TT   512
#define HH   256
#define H2   512
#define LIN  200
#define LPAD 208          // 13 k-tiles * 16
#define FEAT 582
#define FPAD 592          // 37 k-tiles * 16
#define G4   1024
#define SP   58
#define KV   768          // 256 + 512

typedef unsigned long long u64;

// ---------------- device scratch ----------------
__device__ float g_feats[BB * TT * FPAD];
__device__ float g_z    [BB * TT * LPAD];
__device__ float g_G0   [BB * TT * G4];
__device__ float g_hs   [BB * TT * HH];
__device__ float g_h    [2 * BB * HH];
__device__ float g_fcW  [LIN * FPAD];     // zero-padded fc_W
__device__ float g_Wih  [G4 * LPAD];      // zero-padded W_ih

#define NB_LSTM 128
#define GRP     32                          // blocks per barrier group
#define NBAR    513                         // barriers per launch per group
__device__ __align__(128) u64 g_cnt4[4 * 16];   // one counter per 128B

__device__ __forceinline__ float sigf(float x) { return 1.f / (1.f + __expf(-x)); }
__device__ __forceinline__ float tanhfast(float x) {
    float e = __expf(2.f * x);
    return 1.f - 2.f / (e + 1.f);
}

// packed fp32x2 helpers (sm_100+: fma.rn.f32x2)
__device__ __forceinline__ u64 ffma2(u64 a, u64 b, u64 c) {
    u64 d; asm("fma.rn.f32x2 %0, %1, %2, %3;" : "=l"(d) : "l"(a), "l"(b), "l"(c)); return d;
}
__device__ __forceinline__ u64 pack2(float lo, float hi) {
    u64 d; asm("mov.b64 %0, {%1, %2};" : "=l"(d) : "f"(lo), "f"(hi)); return d;
}
__device__ __forceinline__ float2 unpack2(u64 v) {
    float lo, hi; asm("mov.b64 {%0, %1}, %2;" : "=f"(lo), "=f"(hi) : "l"(v));
    return make_float2(lo, hi);
}

// ---------------- kernel 1: features by direct summation + weight padding ----
__global__ void __launch_bounds__(128) feats_k(
    const float* __restrict__ enc, const int* __restrict__ sep,
    const int* __restrict__ pos_ids, const float* __restrict__ pos_emb,
    const float* __restrict__ wl_emb, const float* __restrict__ fcW,
    const float* __restrict__ Wih)
{
    const int m = blockIdx.x;
    const int tid = threadIdx.x;
    if (m >= BB * TT) {
        const int gt = (m - BB * TT) * 128 + tid;   // 0..1023
        for (int i = gt; i < LIN * FPAD; i += 1024) {
            const int n = i / FPAD, k = i - n * FPAD;
            g_fcW[i] = (k < FEAT) ? fcW[n * FEAT + k] : 0.f;
        }
        for (int i = gt; i < G4 * LPAD; i += 1024) {
            const int n = i / LPAD, k = i - n * LPAD;
            g_Wih[i] = (k < LIN) ? Wih[n * LIN + k] : 0.f;
        }
        return;
    }
    const int b = m >> 9;
    const int t = m & (TT - 1);
    int ls = 0;
    const int* sp = sep + b * TT;
    for (int k = t - 1; k >= 1; k--) {
        if (sp[k] > 0) { ls = k; break; }
    }
    int wlen = t - ls; if (wlen < 1) wlen = 1;
    const int wid = (wlen < 7) ? wlen : 7;
    const int lp = pos_ids[b * TT + ls];
    const float inv = 1.0f / (float)wlen;
    float* f = g_feats + (long long)m * FPAD;

    float acc0 = 0.f, acc1 = 0.f, acc2 = 0.f, acc3 = 0.f;
    const float* e = enc + ((long long)b * TT + ls) * H2;
    for (int k = ls; k < t; k++, e += H2) {
        acc0 += e[tid];
        acc1 += e[tid + 128];
        acc2 += e[tid + 256];
        acc3 += e[tid + 384];
    }
    f[50 + tid      ] = acc0 * inv;
    f[50 + tid + 128] = acc1 * inv;
    f[50 + tid + 256] = acc2 * inv;
    f[50 + tid + 384] = acc3 * inv;

    for (int i = tid; i < FPAD; i += 128) {
        if (i < 50)        f[i] = pos_emb[lp * 50 + i];
        else if (i >= 582) f[i] = 0.f;
        else if (i >= 562) f[i] = wl_emb[wid * 20 + (i - 562)];
    }
}

// ---------------- fp32 GEMM with FFMA2: C[M,N] = A[M,K] * B[N,K]^T ----------
template<int MODE, bool KMUL16>
__global__ void __launch_bounds__(128) gemm_k(
    const float* __restrict__ A, const float* __restrict__ Bm,
    const float* __restrict__ bias1, const float* __restrict__ bias2,
    const float* __restrict__ enc, const int* __restrict__ length,
    float* __restrict__ C, int N, int K, int lda, int ldb, int ldc, int nstore)
{
    __shared__ __align__(16) float Asm[16][132];
    __shared__ __align__(16) float Bsm[16][72];
    const int n0 = blockIdx.x * 64;
    const int m0 = blockIdx.y * 128;
    const int tid = threadIdx.x;
    const int tx = tid & 7, ty = tid >> 3;

    const int arow = tid >> 2;
    const int akq  = (tid & 3) * 4;
    const int brow = tid >> 1;
    const int bk0  = (tid & 1) * 8;

    u64 acc[4][8];
    #pragma unroll
    for (int p = 0; p < 4; p++)
        #pragma unroll
        for (int q = 0; q < 8; q++) acc[p][q] = 0ull;

    float bsum[8];
    #pragma unroll
    for (int q = 0; q < 8; q++) {
        const int n = n0 + tx * 8 + q;
        if (MODE == 1)      bsum[q] = (n < N) ? bias1[n] : 0.f;
        else if (MODE == 2) bsum[q] = bias1[n] + bias2[n];
        else                bsum[q] = 0.f;
    }

    const int nkt = (K + 15) >> 4;

    float4 ra[4], rb[2], na[4], nb[2];

    auto loadA = [&](int kt, float4* r) {
        const int k = kt * 16 + akq;
        #pragma unroll
        for (int p = 0; p < 4; p++) {
            const int m = m0 + arow + p * 32;
            if (MODE == 3) {
                const float* src = (k < 256) ? (A + (long long)m * 256 + k)
                                             : (enc + (long long)m * 512 + (k - 256));
                r[p] = *reinterpret_cast<const float4*>(src);
            } else {
                r[p] = *reinterpret_cast<const float4*>(A + (long long)m * lda + k);
            }
        }
    };
    auto loadB = [&](int kt, float4* r) {
        const int n = n0 + brow;
        #pragma unroll
        for (int q = 0; q < 2; q++) {
            const int k = kt * 16 + bk0 + q * 4;
            float4 v = make_float4(0.f, 0.f, 0.f, 0.f);
            if (n < N) {
                if (KMUL16 || k + 3 < K) {
                    v = *reinterpret_cast<const float4*>(Bm + (long long)n * ldb + k);
                } else {
                    float t4[4];
                    #pragma unroll
                    for (int i = 0; i < 4; i++)
                        t4[i] = (k + i < K) ? Bm[(long long)n * ldb + k + i] : 0.f;
                    v = make_float4(t4[0], t4[1], t4[2], t4[3]);
                }
            }
            r[q] = v;
        }
    };

    loadA(0, ra); loadB(0, rb);
    for (int kt = 0; kt < nkt; kt++) {
        #pragma unroll
        for (int p = 0; p < 4; p++) {
            Asm[akq + 0][arow + p * 32] = ra[p].x;
            Asm[akq + 1][arow + p * 32] = ra[p].y;
            Asm[akq + 2][arow + p * 32] = ra[p].z;
            Asm[akq + 3][arow + p * 32] = ra[p].w;
        }
        #pragma unroll
        for (int q = 0; q < 2; q++) {
            Bsm[bk0 + q * 4 + 0][brow] = rb[q].x;
            Bsm[bk0 + q * 4 + 1][brow] = rb[q].y;
            Bsm[bk0 + q * 4 + 2][brow] = rb[q].z;
            Bsm[bk0 + q * 4 + 3][brow] = rb[q].w;
        }
        __syncthreads();
        if (kt + 1 < nkt) { loadA(kt + 1, na); loadB(kt + 1, nb); }
        #pragma unroll
        for (int kk = 0; kk < 16; kk++) {
            const ulonglong2 a01 = *reinterpret_cast<const ulonglong2*>(&Asm[kk][ty * 8]);
            const ulonglong2 a23 = *reinterpret_cast<const ulonglong2*>(&Asm[kk][ty * 8 + 4]);
            const float4 b0 = *reinterpret_cast<const float4*>(&Bsm[kk][tx * 8]);
            const float4 b1 = *reinterpret_cast<const float4*>(&Bsm[kk][tx * 8 + 4]);
            u64 av[4] = {a01.x, a01.y, a23.x, a23.y};
            u64 bd[8] = {pack2(b0.x, b0.x), pack2(b0.y, b0.y), pack2(b0.z, b0.z), pack2(b0.w, b0.w),
                         pack2(b1.x, b1.x), pack2(b1.y, b1.y), pack2(b1.z, b1.z), pack2(b1.w, b1.w)};
            #pragma unroll
            for (int p = 0; p < 4; p++)
                #pragma unroll
                for (int q = 0; q < 8; q++)
                    acc[p][q] = ffma2(av[p], bd[q], acc[p][q]);
        }
        __syncthreads();
        #pragma unroll
        for (int p = 0; p < 4; p++) ra[p] = na[p];
        rb[0] = nb[0]; rb[1] = nb[1];
    }

    const bool vec = (MODE == 2) || (MODE == 1 && n0 + 64 <= N);
    #pragma unroll
    for (int p = 0; p < 4; p++) {
        float2 fr[8];
        #pragma unroll
        for (int q = 0; q < 8; q++) fr[q] = unpack2(acc[p][q]);
        #pragma unroll
        for (int half = 0; half < 2; half++) {
            const int m = m0 + ty * 8 + p * 2 + half;
            const int t = m & (TT - 1);
            float vals[8];
            int lenb = 0;
            if (MODE == 3) lenb = length[m >> 9];
            #pragma unroll
            for (int q = 0; q < 8; q++) {
                const int n = n0 + tx * 8 + q;
                float v = half ? fr[q].y : fr[q].x;
                if (MODE == 1) {
                    if (n < N) { v = tanhfast(v + bsum[q]); if (t == 0) v = 0.f; }
                    else v = 0.f;
                } else if (MODE == 2) {
                    v += bsum[q];
                } else {
                    if (t >= lenb) v = 0.f;
                    if (t == 0 && n == 0) v = -1e30f;
                }
                vals[q] = v;
            }
            float* cp = C + (long long)m * ldc + n0 + tx * 8;
            if (vec) {
                *reinterpret_cast<float4*>(cp)     = make_float4(vals[0], vals[1], vals[2], vals[3]);
                *reinterpret_cast<float4*>(cp + 4) = make_float4(vals[4], vals[5], vals[6], vals[7]);
            } else {
                #pragma unroll
                for (int q = 0; q < 8; q++) {
                    const int n = n0 + tx * 8 + q;
                    if (n < nstore) cp[q] = vals[q];
                }
            }
        }
    }
}

// --------- per-group grid barrier: release-RED arrival + acquire poll -------
__device__ __forceinline__ void gbar_grp(u64* cnt, u64 base, int e) {
    __syncthreads();
    if (threadIdx.x == 0) {
        asm volatile("red.release.gpu.global.add.u64 [%0], %1;"
                     :: "l"(cnt), "l"(1ULL) : "memory");
        const u64 tgt = base + (u64)e * (u64)GRP;
        u64 v;
        do {
            asm volatile("ld.acquire.gpu.global.u64 %0, [%1];"
                         : "=l"(v) : "l"(cnt) : "memory");
        } while (v < tgt);
    }
    __syncthreads();
}

// ---------------- persistent LSTM recurrence: 4x4 blocking, balanced tail ---
// 128 blocks: bt(0..3)*32 batches x ht(0..31)*8 hidden.
// 256 threads: tid = kc*64 + bq*8 + rq.
//   kc 0..3 : k-slice [kc*64, kc*64+64)  AND owner of batch bq+8*kc's cell
//   bq 0..7 / rq 0..7 : batch-lane / hidden unit j = ht*8+rq
// All kc write their 4x4 partials to RED; owner (kc,bq,rq) reduces all 4
// slices for batch bq+8*kc and does exactly ONE cell update + h/hs store.
#define RSTR 20                               // RED slot stride (floats)
__global__ void __launch_bounds__(256, 1) lstm_k(const float* __restrict__ W_hh) {
    extern __shared__ float sm[];
    float* Wsm = sm;                          // [32][260] row = g*8 + hr
    float* Hsm = sm + 32 * 260;               // [32][260] row = batch-in-tile
    float* RED = sm + 64 * 260;               // [4][64][RSTR]
    __shared__ u64 s_base;
    const int bt = blockIdx.x >> 5;
    const int ht = blockIdx.x & 31;
    const int tid = threadIdx.x;
    const int kc = tid >> 6;                  // 0..3
    const int bq = (tid >> 3) & 7;            // 0..7
    const int rq = tid & 7;                   // 0..7
    const int slot = bq * 8 + rq;             // 0..63
    const int j = ht * 8 + rq;
    const int bown = bt * 32 + bq + 8 * kc;   // batch this thread owns
    u64* cnt = &g_cnt4[bt * 16];

    if (tid == 0) {
        const u64 c0 = *(volatile u64*)cnt;
        s_base = c0 - (c0 % (u64)(NBAR * GRP));
    }
    // stage W slice: smem row r = g*8 + hr  <-  W_hh[g*256 + ht*8 + hr]
    #pragma unroll
    for (int i = 0; i < 8; i++) {
        const int idx = tid + i * 256;
        const int r = idx >> 6, k4 = idx & 63;
        const int g = r >> 3, hr = r & 7;
        const float4 w = reinterpret_cast<const float4*>(W_hh)[(g * 256 + ht * 8 + hr) * 64 + k4];
        *reinterpret_cast<float4*>(&Wsm[r * 260 + k4 * 4]) = w;
    }
    float cst = 0.f;
    g_h[bown * HH + j] = 0.f;                 // 256 threads cover 32b x 8h
    __syncthreads();
    const u64 base = s_base;
    gbar_grp(cnt, base, 1);

    const float* Wb = Wsm + rq * 260 + kc * 64;   // gate g at +g*2080
    const float* Hb = Hsm + bq * 260 + kc * 64;   // batch i at +i*2080
    float* wrp = RED + kc * 64 * RSTR + slot * RSTR;
    const float* rdp = RED + slot * RSTR + kc * 4;

    for (int t = 0; t < TT; t++) {
        // stage h tile [32 x 256] into smem
        const float* hb = g_h + (t & 1) * (BB * HH) + bt * 32 * HH;
        #pragma unroll
        for (int i = 0; i < 8; i++) {
            const int idx = tid + i * 256;
            const int r = idx >> 6, k4 = idx & 63;
            *reinterpret_cast<float4*>(&Hsm[r * 260 + k4 * 4]) =
                reinterpret_cast<const float4*>(hb)[r * 64 + k4];
        }
        // G0 for this step (this thread's owned batch; drains during compute)
        float pg[4];
        {
            const float* G = g_G0 + (long long)(bown * TT + t) * G4 + j;
            #pragma unroll
            for (int g = 0; g < 4; g++) pg[g] = G[g * 256];
        }
        __syncthreads();

        u64 acc[4][4];
        #pragma unroll
        for (int i = 0; i < 4; i++)
            #pragma unroll
            for (int g = 0; g < 4; g++) acc[i][g] = 0ull;

        #pragma unroll 4
        for (int k4 = 0; k4 < 16; k4++) {
            ulonglong2 h[4], w[4];
            #pragma unroll
            for (int i = 0; i < 4; i++)
                h[i] = *reinterpret_cast<const ulonglong2*>(Hb + i * 2080 + k4 * 4);
            #pragma unroll
            for (int g = 0; g < 4; g++)
                w[g] = *reinterpret_cast<const ulonglong2*>(Wb + g * 2080 + k4 * 4);
            #pragma unroll
            for (int i = 0; i < 4; i++)
                #pragma unroll
                for (int g = 0; g < 4; g++) {
                    acc[i][g] = ffma2(h[i].x, w[g].x, acc[i][g]);
                    acc[i][g] = ffma2(h[i].y, w[g].y, acc[i][g]);
                }
        }
        // fold packed lanes and publish all 4 batch-partials
        #pragma unroll
        for (int i = 0; i < 4; i++) {
            float4 sv;
            float2 f;
            f = unpack2(acc[i][0]); sv.x = f.x + f.y;
            f = unpack2(acc[i][1]); sv.y = f.x + f.y;
            f = unpack2(acc[i][2]); sv.z = f.x + f.y;
            f = unpack2(acc[i][3]); sv.w = f.x + f.y;
            *reinterpret_cast<float4*>(&wrp[i * 4]) = sv;
        }
        __syncthreads();
        // reduce the 4 k-slices for the owned batch + cell update
        float s0 = pg[0], s1 = pg[1], s2 = pg[2], s3 = pg[3];
        #pragma unroll
        for (int p = 0; p < 4; p++) {
            const float4 v = *reinterpret_cast<const float4*>(rdp + p * 64 * RSTR);
            s0 += v.x; s1 += v.y; s2 += v.z; s3 += v.w;
        }
        const float gi = sigf(s0);
        const float gf = sigf(s1);
        const float gg = tanhfast(s2);
        const float go = sigf(s3);
        cst = gf * cst + gi * gg;
        const float hv = go * tanhfast(cst);
        g_h[((t + 1) & 1) * (BB * HH) + bown * HH + j] = hv;
        g_hs[(long long)(bown * TT + t) * HH + j] = hv;
        gbar_grp(cnt, base, 2 + t);
    }
}

// ---------------- host launch ----------------
extern "C" void kernel_launch(void* const* d_in, const int* in_sizes, int n_in,
                              void* d_out, int out_size) {
    const float* enc         = (const float*)d_in[0];
    const int*   sep_mask    = (const int*)d_in[1];
    const int*   pos_ids     = (const int*)d_in[2];
    const int*   length      = (const int*)d_in[3];
    const float* pos_emb     = (const float*)d_in[4];
    const float* wordlen_emb = (const float*)d_in[5];
    const float* fc_W        = (const float*)d_in[6];
    const float* fc_b        = (const float*)d_in[7];
    const float* W_ih        = (const float*)d_in[8];
    const float* W_hh        = (const float*)d_in[9];
    const float* b_ih        = (const float*)d_in[10];
    const float* b_hh        = (const float*)d_in[11];
    const float* combine_W   = (const float*)d_in[12];
    float* out = (float*)d_out;

    float* d_feats; cudaGetSymbolAddress((void**)&d_feats, g_feats);
    float* d_fcW;   cudaGetSymbolAddress((void**)&d_fcW, g_fcW);
    float* d_Wih;   cudaGetSymbolAddress((void**)&d_Wih, g_Wih);
    float* d_z;     cudaGetSymbolAddress((void**)&d_z, g_z);
    float* d_G0;    cudaGetSymbolAddress((void**)&d_G0, g_G0);
    float* d_hs;    cudaGetSymbolAddress((void**)&d_hs, g_hs);

    // launch 1: features (direct word-mean) + weight padding
    feats_k<<<BB * TT + 8, 128>>>(enc, sep_mask, pos_ids, pos_emb,
                                  wordlen_emb, fc_W, W_ih);

    // launch 2: GEMM1  z = tanh(feats @ g_fcW^T + fc_b)   M=65536 N=200 K=592
    gemm_k<1, true><<<dim3(4, 512), 128>>>(
        d_feats, d_fcW, fc_b, nullptr, nullptr, nullptr, d_z,
        LIN, FPAD, FPAD, FPAD, LPAD, LPAD);

    // launch 3: GEMM2  G0 = z @ g_Wih^T + b_ih + b_hh     M=65536 N=1024 K=208
    gemm_k<2, true><<<dim3(16, 512), 128>>>(
        d_z, d_Wih, b_ih, b_hh, nullptr, nullptr, d_G0,
        G4, LPAD, LPAD, LPAD, G4, G4);

    // launch 4 (ncu capture slot): LSTM recurrence
    const int lstm_smem = (64 * 260 + 4 * 64 * RSTR) * (int)sizeof(float);
    cudaFuncSetAttribute(lstm_k, cudaFuncAttributeMaxDynamicSharedMemorySize, lstm_smem);
    lstm_k<<<NB_LSTM, 256, lstm_smem>>>(W_hh);

    // launch 5: GEMM3  logits = [hs|enc] @ combine_W^T + mask
    gemm_k<3, true><<<dim3(1, 512), 128>>>(
        d_hs, combine_W, nullptr, nullptr, enc, length, out,
        SP, KV, 0, KV, SP, SP);
}

// round 17
// speedup vs baseline: 2.2602x; 1.0042x over previous
#include <cuda_runtime.h>
#include <cuda_bf16.h>
#include <cstdint>

// Problem dims
#define BB   128
#define TT   512
#define HH   256
#define H2   512
#define LIN  200
#define LPAD 208          // 13 k-tiles * 16
#define FEAT 582
#define FPAD 592          // 37 k-tiles * 16
#define G4   1024
#define SP   58
#define KV   768          // 256 + 512

typedef unsigned long long u64;

// ---------------- device scratch ----------------
__device__ float g_feats[BB * TT * FPAD];
__device__ float g_z    [BB * TT * LPAD];
__device__ float g_G0   [BB * TT * G4];
__device__ float g_hs   [BB * TT * HH];
__device__ float g_h    [2 * BB * HH];
__device__ float g_fcW  [LIN * FPAD];     // zero-padded fc_W
__device__ float g_Wih  [G4 * LPAD];      // zero-padded W_ih

#define NB_LSTM 128
#define GRP     32                          // blocks per barrier group
#define NBAR    513                         // barriers per launch per group
__device__ __align__(128) u64 g_cnt4[4 * 16];   // one counter per 128B

__device__ __forceinline__ float sigf(float x) { return 1.f / (1.f + __expf(-x)); }
__device__ __forceinline__ float tanhfast(float x) {
    float e = __expf(2.f * x);
    return 1.f - 2.f / (e + 1.f);
}

// packed fp32x2 helpers (sm_100+: fma.rn.f32x2)
__device__ __forceinline__ u64 ffma2(u64 a, u64 b, u64 c) {
    u64 d; asm("fma.rn.f32x2 %0, %1, %2, %3;" : "=l"(d) : "l"(a), "l"(b), "l"(c)); return d;
}
__device__ __forceinline__ u64 pack2(float lo, float hi) {
    u64 d; asm("mov.b64 %0, {%1, %2};" : "=l"(d) : "f"(lo), "f"(hi)); return d;
}
__device__ __forceinline__ float2 unpack2(u64 v) {
    float lo, hi; asm("mov.b64 {%0, %1}, %2;" : "=f"(lo), "=f"(hi) : "l"(v));
    return make_float2(lo, hi);
}

// ---------------- kernel 1: features by direct summation + weight padding ----
__global__ void __launch_bounds__(128) feats_k(
    const float* __restrict__ enc, const int* __restrict__ sep,
    const int* __restrict__ pos_ids, const float* __restrict__ pos_emb,
    const float* __restrict__ wl_emb, const float* __restrict__ fcW,
    const float* __restrict__ Wih)
{
    const int m = blockIdx.x;
    const int tid = threadIdx.x;
    if (m >= BB * TT) {
        const int gt = (m - BB * TT) * 128 + tid;   // 0..1023
        for (int i = gt; i < LIN * FPAD; i += 1024) {
            const int n = i / FPAD, k = i - n * FPAD;
            g_fcW[i] = (k < FEAT) ? fcW[n * FEAT + k] : 0.f;
        }
        for (int i = gt; i < G4 * LPAD; i += 1024) {
            const int n = i / LPAD, k = i - n * LPAD;
            g_Wih[i] = (k < LIN) ? Wih[n * LIN + k] : 0.f;
        }
        return;
    }
    const int b = m >> 9;
    const int t = m & (TT - 1);
    int ls = 0;
    const int* sp = sep + b * TT;
    for (int k = t - 1; k >= 1; k--) {
        if (sp[k] > 0) { ls = k; break; }
    }
    int wlen = t - ls; if (wlen < 1) wlen = 1;
    const int wid = (wlen < 7) ? wlen : 7;
    const int lp = pos_ids[b * TT + ls];
    const float inv = 1.0f / (float)wlen;
    float* f = g_feats + (long long)m * FPAD;

    float acc0 = 0.f, acc1 = 0.f, acc2 = 0.f, acc3 = 0.f;
    const float* e = enc + ((long long)b * TT + ls) * H2;
    for (int k = ls; k < t; k++, e += H2) {
        acc0 += e[tid];
        acc1 += e[tid + 128];
        acc2 += e[tid + 256];
        acc3 += e[tid + 384];
    }
    f[50 + tid      ] = acc0 * inv;
    f[50 + tid + 128] = acc1 * inv;
    f[50 + tid + 256] = acc2 * inv;
    f[50 + tid + 384] = acc3 * inv;

    for (int i = tid; i < FPAD; i += 128) {
        if (i < 50)        f[i] = pos_emb[lp * 50 + i];
        else if (i >= 582) f[i] = 0.f;
        else if (i >= 562) f[i] = wl_emb[wid * 20 + (i - 562)];
    }
}

// ---------------- fp32 GEMM with FFMA2: C[M,N] = A[M,K] * B[N,K]^T ----------
template<int MODE, bool KMUL16>
__global__ void __launch_bounds__(128) gemm_k(
    const float* __restrict__ A, const float* __restrict__ Bm,
    const float* __restrict__ bias1, const float* __restrict__ bias2,
    const float* __restrict__ enc, const int* __restrict__ length,
    float* __restrict__ C, int N, int K, int lda, int ldb, int ldc, int nstore)
{
    __shared__ __align__(16) float Asm[16][132];
    __shared__ __align__(16) float Bsm[16][72];
    const int n0 = blockIdx.x * 64;
    const int m0 = blockIdx.y * 128;
    const int tid = threadIdx.x;
    const int tx = tid & 7, ty = tid >> 3;

    const int arow = tid >> 2;
    const int akq  = (tid & 3) * 4;
    const int brow = tid >> 1;
    const int bk0  = (tid & 1) * 8;

    u64 acc[4][8];
    #pragma unroll
    for (int p = 0; p < 4; p++)
        #pragma unroll
        for (int q = 0; q < 8; q++) acc[p][q] = 0ull;

    float bsum[8];
    #pragma unroll
    for (int q = 0; q < 8; q++) {
        const int n = n0 + tx * 8 + q;
        if (MODE == 1)      bsum[q] = (n < N) ? bias1[n] : 0.f;
        else if (MODE == 2) bsum[q] = bias1[n] + bias2[n];
        else                bsum[q] = 0.f;
    }

    const int nkt = (K + 15) >> 4;

    float4 ra[4], rb[2], na[4], nb[2];

    auto loadA = [&](int kt, float4* r) {
        const int k = kt * 16 + akq;
        #pragma unroll
        for (int p = 0; p < 4; p++) {
            const int m = m0 + arow + p * 32;
            if (MODE == 3) {
                const float* src = (k < 256) ? (A + (long long)m * 256 + k)
                                             : (enc + (long long)m * 512 + (k - 256));
                r[p] = *reinterpret_cast<const float4*>(src);
            } else {
                r[p] = *reinterpret_cast<const float4*>(A + (long long)m * lda + k);
            }
        }
    };
    auto loadB = [&](int kt, float4* r) {
        const int n = n0 + brow;
        #pragma unroll
        for (int q = 0; q < 2; q++) {
            const int k = kt * 16 + bk0 + q * 4;
            float4 v = make_float4(0.f, 0.f, 0.f, 0.f);
            if (n < N) {
                if (KMUL16 || k + 3 < K) {
                    v = *reinterpret_cast<const float4*>(Bm + (long long)n * ldb + k);
                } else {
                    float t4[4];
                    #pragma unroll
                    for (int i = 0; i < 4; i++)
                        t4[i] = (k + i < K) ? Bm[(long long)n * ldb + k + i] : 0.f;
                    v = make_float4(t4[0], t4[1], t4[2], t4[3]);
                }
            }
            r[q] = v;
        }
    };

    loadA(0, ra); loadB(0, rb);
    for (int kt = 0; kt < nkt; kt++) {
        #pragma unroll
        for (int p = 0; p < 4; p++) {
            Asm[akq + 0][arow + p * 32] = ra[p].x;
            Asm[akq + 1][arow + p * 32] = ra[p].y;
            Asm[akq + 2][arow + p * 32] = ra[p].z;
            Asm[akq + 3][arow + p * 32] = ra[p].w;
        }
        #pragma unroll
        for (int q = 0; q < 2; q++) {
            Bsm[bk0 + q * 4 + 0][brow] = rb[q].x;
            Bsm[bk0 + q * 4 + 1][brow] = rb[q].y;
            Bsm[bk0 + q * 4 + 2][brow] = rb[q].z;
            Bsm[bk0 + q * 4 + 3][brow] = rb[q].w;
        }
        __syncthreads();
        if (kt + 1 < nkt) { loadA(kt + 1, na); loadB(kt + 1, nb); }
        #pragma unroll
        for (int kk = 0; kk < 16; kk++) {
            const ulonglong2 a01 = *reinterpret_cast<const ulonglong2*>(&Asm[kk][ty * 8]);
            const ulonglong2 a23 = *reinterpret_cast<const ulonglong2*>(&Asm[kk][ty * 8 + 4]);
            const float4 b0 = *reinterpret_cast<const float4*>(&Bsm[kk][tx * 8]);
            const float4 b1 = *reinterpret_cast<const float4*>(&Bsm[kk][tx * 8 + 4]);
            u64 av[4] = {a01.x, a01.y, a23.x, a23.y};
            u64 bd[8] = {pack2(b0.x, b0.x), pack2(b0.y, b0.y), pack2(b0.z, b0.z), pack2(b0.w, b0.w),
                         pack2(b1.x, b1.x), pack2(b1.y, b1.y), pack2(b1.z, b1.z), pack2(b1.w, b1.w)};
            #pragma unroll
            for (int p = 0; p < 4; p++)
                #pragma unroll
                for (int q = 0; q < 8; q++)
                    acc[p][q] = ffma2(av[p], bd[q], acc[p][q]);
        }
        __syncthreads();
        #pragma unroll
        for (int p = 0; p < 4; p++) ra[p] = na[p];
        rb[0] = nb[0]; rb[1] = nb[1];
    }

    const bool vec = (MODE == 2) || (MODE == 1 && n0 + 64 <= N);
    #pragma unroll
    for (int p = 0; p < 4; p++) {
        float2 fr[8];
        #pragma unroll
        for (int q = 0; q < 8; q++) fr[q] = unpack2(acc[p][q]);
        #pragma unroll
        for (int half = 0; half < 2; half++) {
            const int m = m0 + ty * 8 + p * 2 + half;
            const int t = m & (TT - 1);
            float vals[8];
            int lenb = 0;
            if (MODE == 3) lenb = length[m >> 9];
            #pragma unroll
            for (int q = 0; q < 8; q++) {
                const int n = n0 + tx * 8 + q;
                float v = half ? fr[q].y : fr[q].x;
                if (MODE == 1) {
                    if (n < N) { v = tanhfast(v + bsum[q]); if (t == 0) v = 0.f; }
                    else v = 0.f;
                } else if (MODE == 2) {
                    v += bsum[q];
                } else {
                    if (t >= lenb) v = 0.f;
                    if (t == 0 && n == 0) v = -1e30f;
                }
                vals[q] = v;
            }
            float* cp = C + (long long)m * ldc + n0 + tx * 8;
            if (vec) {
                *reinterpret_cast<float4*>(cp)     = make_float4(vals[0], vals[1], vals[2], vals[3]);
                *reinterpret_cast<float4*>(cp + 4) = make_float4(vals[4], vals[5], vals[6], vals[7]);
            } else {
                #pragma unroll
                for (int q = 0; q < 8; q++) {
                    const int n = n0 + tx * 8 + q;
                    if (n < nstore) cp[q] = vals[q];
                }
            }
        }
    }
}

// --------- per-group grid barrier: release-RED arrival + acquire poll -------
__device__ __forceinline__ void gbar_grp(u64* cnt, u64 base, int e) {
    __syncthreads();
    if (threadIdx.x == 0) {
        asm volatile("red.release.gpu.global.add.u64 [%0], %1;"
                     :: "l"(cnt), "l"(1ULL) : "memory");
        const u64 tgt = base + (u64)e * (u64)GRP;
        u64 v;
        do {
            asm volatile("ld.acquire.gpu.global.u64 %0, [%1];"
                         : "=l"(v) : "l"(cnt) : "memory");
        } while (v < tgt);
    }
    __syncthreads();
}

// ------- persistent LSTM: 4x4 blocking, 8 k-slices, 512 threads -------------
// 128 blocks: bt(0..3)*32 batches x ht(0..31)*8 hidden.
// 512 threads: tid = kc*64 + bq*8 + rq.
//   kc 0..7 : k-slice [kc*32, kc*32+32); kc<4 additionally owns batch bq+8*kc
//   bq 0..7 / rq 0..7 : batch-lane / hidden unit j = ht*8+rq
// All kc write 4x4 partials to RED; owner reduces 8 slices, one cell update.
#define RSTR 20                               // RED slot stride (floats)
#define KSL  8
__global__ void __launch_bounds__(512, 1) lstm_k(const float* __restrict__ W_hh) {
    extern __shared__ float sm[];
    float* Wsm = sm;                          // [32][260] row = g*8 + hr
    float* Hsm = sm + 32 * 260;               // [32][260] row = batch-in-tile
    float* RED = sm + 64 * 260;               // [8][64][RSTR]
    __shared__ u64 s_base;
    const int bt = blockIdx.x >> 5;
    const int ht = blockIdx.x & 31;
    const int tid = threadIdx.x;
    const int kc = tid >> 6;                  // 0..7
    const int bq = (tid >> 3) & 7;            // 0..7
    const int rq = tid & 7;                   // 0..7
    const int slot = bq * 8 + rq;             // 0..63
    const int j = ht * 8 + rq;
    const bool owner = (kc < 4);
    const int bown = bt * 32 + bq + 8 * (kc & 3);   // owned batch (kc<4)
    u64* cnt = &g_cnt4[bt * 16];

    if (tid == 0) {
        const u64 c0 = *(volatile u64*)cnt;
        s_base = c0 - (c0 % (u64)(NBAR * GRP));
    }
    // stage W slice: smem row r = g*8 + hr  <-  W_hh[g*256 + ht*8 + hr]
    #pragma unroll
    for (int i = 0; i < 4; i++) {
        const int idx = tid + i * 512;
        const int r = idx >> 6, k4 = idx & 63;
        const int g = r >> 3, hr = r & 7;
        const float4 w = reinterpret_cast<const float4*>(W_hh)[(g * 256 + ht * 8 + hr) * 64 + k4];
        *reinterpret_cast<float4*>(&Wsm[r * 260 + k4 * 4]) = w;
    }
    float cst = 0.f;
    if (owner) g_h[bown * HH + j] = 0.f;      // 256 owners cover 32b x 8h
    __syncthreads();
    const u64 base = s_base;
    gbar_grp(cnt, base, 1);

    const float* Wb = Wsm + rq * 260 + kc * 32;   // gate g at +g*2080
    const float* Hb = Hsm + bq * 260 + kc * 32;   // batch i at +i*2080
    float* wrp = RED + kc * 64 * RSTR + slot * RSTR;
    const float* rdp = RED + slot * RSTR + (kc & 3) * 4;

    for (int t = 0; t < TT; t++) {
        // stage h tile [32 x 256] into smem
        const float* hb = g_h + (t & 1) * (BB * HH) + bt * 32 * HH;
        #pragma unroll
        for (int i = 0; i < 4; i++) {
            const int idx = tid + i * 512;
            const int r = idx >> 6, k4 = idx & 63;
            *reinterpret_cast<float4*>(&Hsm[r * 260 + k4 * 4]) =
                reinterpret_cast<const float4*>(hb)[r * 64 + k4];
        }
        // G0 for this step (owners only; drains during compute)
        float pg[4];
        if (owner) {
            const float* G = g_G0 + (long long)(bown * TT + t) * G4 + j;
            #pragma unroll
            for (int g = 0; g < 4; g++) pg[g] = G[g * 256];
        }
        __syncthreads();

        u64 acc[4][4];
        #pragma unroll
        for (int i = 0; i < 4; i++)
            #pragma unroll
            for (int g = 0; g < 4; g++) acc[i][g] = 0ull;

        #pragma unroll
        for (int k4 = 0; k4 < 8; k4++) {
            ulonglong2 h[4], w[4];
            #pragma unroll
            for (int i = 0; i < 4; i++)
                h[i] = *reinterpret_cast<const ulonglong2*>(Hb + i * 2080 + k4 * 4);
            #pragma unroll
            for (int g = 0; g < 4; g++)
                w[g] = *reinterpret_cast<const ulonglong2*>(Wb + g * 2080 + k4 * 4);
            #pragma unroll
            for (int i = 0; i < 4; i++)
                #pragma unroll
                for (int g = 0; g < 4; g++) {
                    acc[i][g] = ffma2(h[i].x, w[g].x, acc[i][g]);
                    acc[i][g] = ffma2(h[i].y, w[g].y, acc[i][g]);
                }
        }
        // fold packed lanes and publish all 4 batch-partials
        #pragma unroll
        for (int i = 0; i < 4; i++) {
            float4 sv;
            float2 f;
            f = unpack2(acc[i][0]); sv.x = f.x + f.y;
            f = unpack2(acc[i][1]); sv.y = f.x + f.y;
            f = unpack2(acc[i][2]); sv.z = f.x + f.y;
            f = unpack2(acc[i][3]); sv.w = f.x + f.y;
            *reinterpret_cast<float4*>(&wrp[i * 4]) = sv;
        }
        __syncthreads();
        if (owner) {
            // reduce the 8 k-slices for the owned batch + cell update
            float s0 = pg[0], s1 = pg[1], s2 = pg[2], s3 = pg[3];
            #pragma unroll
            for (int p = 0; p < KSL; p++) {
                const float4 v = *reinterpret_cast<const float4*>(rdp + p * 64 * RSTR);
                s0 += v.x; s1 += v.y; s2 += v.z; s3 += v.w;
            }
            const float gi = sigf(s0);
            const float gf = sigf(s1);
            const float gg = tanhfast(s2);
            const float go = sigf(s3);
            cst = gf * cst + gi * gg;
            const float hv = go * tanhfast(cst);
            g_h[((t + 1) & 1) * (BB * HH) + bown * HH + j] = hv;
            g_hs[(long long)(bown * TT + t) * HH + j] = hv;
        }
        gbar_grp(cnt, base, 2 + t);
    }
}

// ---------------- host launch ----------------
extern "C" void kernel_launch(void* const* d_in, const int* in_sizes, int n_in,
                              void* d_out, int out_size) {
    const float* enc         = (const float*)d_in[0];
    const int*   sep_mask    = (const int*)d_in[1];
    const int*   pos_ids     = (const int*)d_in[2];
    const int*   length      = (const int*)d_in[3];
    const float* pos_emb     = (const float*)d_in[4];
    const float* wordlen_emb = (const float*)d_in[5];
    const float* fc_W        = (const float*)d_in[6];
    const float* fc_b        = (const float*)d_in[7];
    const float* W_ih        = (const float*)d_in[8];
    const float* W_hh        = (const float*)d_in[9];
    const float* b_ih        = (const float*)d_in[10];
    const float* b_hh        = (const float*)d_in[11];
    const float* combine_W   = (const float*)d_in[12];
    float* out = (float*)d_out;

    float* d_feats; cudaGetSymbolAddress((void**)&d_feats, g_feats);
    float* d_fcW;   cudaGetSymbolAddress((void**)&d_fcW, g_fcW);
    float* d_Wih;   cudaGetSymbolAddress((void**)&d_Wih, g_Wih);
    float* d_z;     cudaGetSymbolAddress((void**)&d_z, g_z);
    float* d_G0;    cudaGetSymbolAddress((void**)&d_G0, g_G0);
    float* d_hs;    cudaGetSymbolAddress((void**)&d_hs, g_hs);

    // launch 1: features (direct word-mean) + weight padding
    feats_k<<<BB * TT + 8, 128>>>(enc, sep_mask, pos_ids, pos_emb,
                                  wordlen_emb, fc_W, W_ih);

    // launch 2: GEMM1  z = tanh(feats @ g_fcW^T + fc_b)   M=65536 N=200 K=592
    gemm_k<1, true><<<dim3(4, 512), 128>>>(
        d_feats, d_fcW, fc_b, nullptr, nullptr, nullptr, d_z,
        LIN, FPAD, FPAD, FPAD, LPAD, LPAD);

    // launch 3: GEMM2  G0 = z @ g_Wih^T + b_ih + b_hh     M=65536 N=1024 K=208
    gemm_k<2, true><<<dim3(16, 512), 128>>>(
        d_z, d_Wih, b_ih, b_hh, nullptr, nullptr, d_G0,
        G4, LPAD, LPAD, LPAD, G4, G4);

    // launch 4 (ncu capture slot): LSTM recurrence (512 thr, 8 k-slices)
    const int lstm_smem = (64 * 260 + KSL * 64 * RSTR) * (int)sizeof(float);
    cudaFuncSetAttribute(lstm_k, cudaFuncAttributeMaxDynamicSharedMemorySize, lstm_smem);
    lstm_k<<<NB_LSTM, 512, lstm_smem>>>(W_hh);

    // launch 5: GEMM3  logits = [hs|enc] @ combine_W^T + mask
    gemm_k<3, true><<<dim3(1, 512), 128>>>(
        d_hs, combine_W, nullptr, nullptr, enc, length, out,
        SP, KV, 0, KV, SP, SP);
}